// round 10
// baseline (speedup 1.0000x reference)
#include <cuda_runtime.h>
#include <cuda_bf16.h>
#include <stdint.h>
#include <math.h>

// ---------------------------------------------------------------------------
#define CDIM     256
#define MTILE    128
#define NTHREADS 256
#define NQKV     768
#define TOTTOK   131072
#define SA       264          // A tile stride in halves (528B rows; LDSM conflict-free)

#define SB_ROW      144       // B stage row stride bytes (128B data + 16B pad)
#define STAGE_HALF  (128 * SB_ROW)      // 18432 (one weight array)
#define STAGE_BYTES (2 * STAGE_HALF)    // 36864 (hi + lo)

// shared memory layout (bytes)
#define S_AH   0                          // 128 x SA halves = 67584
#define S_AL   67584
#define S_BST  135168                     // 2 stages x 36864 = 73728
#define S_BIAS 208896                     // 1024 floats
#define S_RED  212992                     // softmax scratch
#define SMEM_BYTES 214016

// ---------------------------------------------------------------------------
__device__ float          g_qkv[(size_t)TOTTOK * NQKV];
__device__ __nv_bfloat16  g_whi[(NQKV + CDIM) * CDIM];
__device__ __nv_bfloat16  g_wlo[(NQKV + CDIM) * CDIM];

// ---------------------------------------------------------------------------
#define MMA16816(c, a, b0, b1) \
    asm volatile("mma.sync.aligned.m16n8k16.row.col.f32.bf16.bf16.f32 " \
        "{%0,%1,%2,%3}, {%4,%5,%6,%7}, {%8,%9}, {%0,%1,%2,%3};" \
        : "+f"((c)[0]), "+f"((c)[1]), "+f"((c)[2]), "+f"((c)[3]) \
        : "r"((a)[0]), "r"((a)[1]), "r"((a)[2]), "r"((a)[3]), \
          "r"(b0), "r"(b1))

#define LDSM4(r, a) \
    asm volatile("ldmatrix.sync.aligned.m8n8.x4.shared.b16 {%0,%1,%2,%3}, [%4];" \
        : "=r"((r)[0]), "=r"((r)[1]), "=r"((r)[2]), "=r"((r)[3]) : "r"(a))

#define CP_ASYNC16(dst, src) \
    asm volatile("cp.async.cg.shared.global [%0], [%1], 16;" \
        :: "r"(dst), "l"(src) : "memory")
#define CP_COMMIT() asm volatile("cp.async.commit_group;" ::: "memory")
#define CP_WAIT0()  asm volatile("cp.async.wait_group 0;" ::: "memory")

#define SPLIT4(a0,a1,a2,a3,HI0,HI1,LO0,LO1) do { \
    __nv_bfloat16 _h0=__float2bfloat16(a0), _h1=__float2bfloat16(a1); \
    __nv_bfloat16 _h2=__float2bfloat16(a2), _h3=__float2bfloat16(a3); \
    __nv_bfloat16 _l0=__float2bfloat16((a0)-__bfloat162float(_h0)); \
    __nv_bfloat16 _l1=__float2bfloat16((a1)-__bfloat162float(_h1)); \
    __nv_bfloat16 _l2=__float2bfloat16((a2)-__bfloat162float(_h2)); \
    __nv_bfloat16 _l3=__float2bfloat16((a3)-__bfloat162float(_h3)); \
    HI0 = ((uint32_t)__bfloat16_as_ushort(_h1) << 16) | __bfloat16_as_ushort(_h0); \
    HI1 = ((uint32_t)__bfloat16_as_ushort(_h3) << 16) | __bfloat16_as_ushort(_h2); \
    LO0 = ((uint32_t)__bfloat16_as_ushort(_l1) << 16) | __bfloat16_as_ushort(_l0); \
    LO1 = ((uint32_t)__bfloat16_as_ushort(_l3) << 16) | __bfloat16_as_ushort(_l2); \
} while (0)

// ---------------------------------------------------------------------------
__global__ void ga_prep_w(const float* __restrict__ qkv_w,
                          const float* __restrict__ out_w) {
    int i = blockIdx.x * blockDim.x + threadIdx.x;     // < 1024*256
    float v = (i < NQKV * CDIM) ? qkv_w[i] : out_w[i - NQKV * CDIM];
    __nv_bfloat16 h = __float2bfloat16(v);
    g_whi[i] = h;
    g_wlo[i] = __float2bfloat16(v - __bfloat162float(h));
}

// ---------------------------------------------------------------------------
// stage s (32 total): chunk = s>>2 (0..5 QKV, 6..7 out), kc = s&3.
// Loads BOTH whi and wlo 128x64-half k-chunks into ring buffer (s&1).
__device__ __forceinline__ void issue_stage(int s, uint32_t sbst, int tid) {
    if (s < 32) {
        const int kc   = s & 3;
        const int row0 = (s < 24) ? (s >> 2) * 128 : NQKV + ((s >> 2) - 6) * 128;
        const size_t src = ((size_t)row0 << 8) + kc * 64;
        const uint32_t dst = sbst + (uint32_t)(s & 1) * STAGE_BYTES;
        #pragma unroll
        for (int k = 0; k < 4; k++) {
            const int i  = tid + k * NTHREADS;        // 0..1023
            const int r  = i >> 3, cq = i & 7;
            const size_t so = src + ((size_t)r << 8) + cq * 8;
            CP_ASYNC16(dst + r * SB_ROW + cq * 16, (const void*)(g_whi + so));
            CP_ASYNC16(dst + STAGE_HALF + r * SB_ROW + cq * 16,
                       (const void*)(g_wlo + so));
        }
    }
    CP_COMMIT();
}

// merged 3-term stage: c += Ah*Bh + Al*Bh + Ah*Bl  (4 k-steps of 16)
__device__ __forceinline__ void stage_mma(uint32_t aBh0, uint32_t aAh0,
                                          uint32_t aAl0, uint32_t kbase,
                                          float c[4][4][4]) {
    const uint32_t aBh1 = aBh0 + 16 * SB_ROW;
    const uint32_t aBl0 = aBh0 + STAGE_HALF;
    const uint32_t aBl1 = aBl0 + 16 * SB_ROW;
    #pragma unroll
    for (int ks = 0; ks < 4; ks++) {
        const uint32_t kb  = (uint32_t)(ks * 32);
        const uint32_t kba = kbase + kb;
        uint32_t bh0[4], bh1[4], bl0[4], bl1[4];
        LDSM4(bh0, aBh0 + kb); LDSM4(bh1, aBh1 + kb);
        LDSM4(bl0, aBl0 + kb); LDSM4(bl1, aBl1 + kb);
        uint32_t ah[4][4], al[4][4];
        #pragma unroll
        for (int mt = 0; mt < 4; mt++) {
            LDSM4(ah[mt], aAh0 + mt * (16 * SA * 2) + kba);
            LDSM4(al[mt], aAl0 + mt * (16 * SA * 2) + kba);
        }
        #pragma unroll
        for (int mt = 0; mt < 4; mt++) {
            MMA16816(c[mt][0], ah[mt], bh0[0], bh0[1]);
            MMA16816(c[mt][1], ah[mt], bh0[2], bh0[3]);
            MMA16816(c[mt][2], ah[mt], bh1[0], bh1[1]);
            MMA16816(c[mt][3], ah[mt], bh1[2], bh1[3]);
        }
        #pragma unroll
        for (int mt = 0; mt < 4; mt++) {
            MMA16816(c[mt][0], al[mt], bh0[0], bh0[1]);
            MMA16816(c[mt][1], al[mt], bh0[2], bh0[3]);
            MMA16816(c[mt][2], al[mt], bh1[0], bh1[1]);
            MMA16816(c[mt][3], al[mt], bh1[2], bh1[3]);
        }
        #pragma unroll
        for (int mt = 0; mt < 4; mt++) {
            MMA16816(c[mt][0], ah[mt], bl0[0], bl0[1]);
            MMA16816(c[mt][1], ah[mt], bl0[2], bl0[3]);
            MMA16816(c[mt][2], ah[mt], bl1[0], bl1[1]);
            MMA16816(c[mt][3], ah[mt], bl1[2], bl1[3]);
        }
    }
}

#define ZERO_C(c) do { \
    _Pragma("unroll") for (int mt = 0; mt < 4; mt++) \
    _Pragma("unroll") for (int jt = 0; jt < 4; jt++) \
    _Pragma("unroll") for (int q = 0; q < 4; q++) (c)[mt][jt][q] = 0.f; \
} while (0)

// ---------------------------------------------------------------------------
__global__ void __launch_bounds__(NTHREADS, 1)
ga_main(const float* __restrict__ x,
        const float* __restrict__ qkv_b,
        const float* __restrict__ out_b,
        const float* __restrict__ ln_g,
        const float* __restrict__ ln_b,
        float* __restrict__ out)
{
    extern __shared__ char smem[];
    __nv_bfloat16* Ah    = (__nv_bfloat16*)(smem + S_AH);
    __nv_bfloat16* Al    = (__nv_bfloat16*)(smem + S_AL);
    float*         s_bias= (float*)(smem + S_BIAS);
    float*         s_red = (float*)(smem + S_RED);

    const int tid  = threadIdx.x;
    const int wid  = tid >> 5;
    const int lane = tid & 31;
    const int warp_m = wid & 1;          // 2 x M64
    const int warp_n = wid >> 1;         // 4 x N32
    const int tok0 = blockIdx.x * MTILE;

    const uint32_t sbst = (uint32_t)__cvta_generic_to_shared(smem + S_BST);

    // LDSM lane addresses
    uint32_t aAh0, aAl0, boff0;
    {
        const int arow  = warp_m * 64 + (lane & 15);
        const int akoff = (lane >> 4) << 3;                 // halves
        aAh0 = (uint32_t)__cvta_generic_to_shared(Ah + arow * SA + akoff);
        aAl0 = (uint32_t)__cvta_generic_to_shared(Al + arow * SA + akoff);
        const int brow  = (lane & 7) + ((lane >> 4) << 3);
        const int bkoff = ((lane >> 3) & 1) << 3;           // halves
        boff0 = (uint32_t)((warp_n * 32 + brow) * SB_ROW + bkoff * 2);
    }

    // prologue: prefetch stage 0 (overlaps LN below)
    issue_stage(0, sbst, tid);

    for (int i = tid; i < 1024; i += NTHREADS)
        s_bias[i] = (i < NQKV) ? __ldg(qkv_b + i) : __ldg(out_b + i - NQKV);

    // ---- Phase A: LN + bf16 split -> Ah/Al (2 threads per token)
    {
        const int t = tid >> 1, sub = tid & 1;
        const float* xr = x + ((size_t)(tok0 + t) << 8) + sub * 128;
        float s = 0.f, s2 = 0.f;
        #pragma unroll 8
        for (int j = 0; j < 32; j++) {
            float4 v = __ldg((const float4*)xr + j);
            s  += v.x + v.y + v.z + v.w;
            s2 += v.x * v.x + v.y * v.y + v.z * v.z + v.w * v.w;
        }
        s  += __shfl_xor_sync(0xffffffffu, s, 1);
        s2 += __shfl_xor_sync(0xffffffffu, s2, 1);
        const float mean = s * (1.f / 256.f);
        const float rstd = rsqrtf(s2 * (1.f / 256.f) - mean * mean + 1e-5f);
        __nv_bfloat16* ah = Ah + t * SA + sub * 128;
        __nv_bfloat16* al = Al + t * SA + sub * 128;
        #pragma unroll 4
        for (int j = 0; j < 32; j++) {
            const int k = j * 4;
            float4 v  = __ldg((const float4*)xr + j);
            float4 g4 = __ldg((const float4*)(ln_g + sub * 128 + k));
            float4 b4 = __ldg((const float4*)(ln_b + sub * 128 + k));
            float a0 = (v.x - mean) * rstd * g4.x + b4.x;
            float a1 = (v.y - mean) * rstd * g4.y + b4.y;
            float a2 = (v.z - mean) * rstd * g4.z + b4.z;
            float a3 = (v.w - mean) * rstd * g4.w + b4.w;
            uint32_t h0, h1, l0, l1;
            SPLIT4(a0, a1, a2, a3, h0, h1, l0, l1);
            *(uint2*)(ah + k) = make_uint2(h0, h1);
            *(uint2*)(al + k) = make_uint2(l0, l1);
        }
    }

    float c[4][4][4];

    // ---- Phase B: QKV projection (stages 0..23, 4 per N-chunk of 128)
    for (int s = 0; s < 24; s++) {
        if ((s & 3) == 0) ZERO_C(c);
        CP_WAIT0();                       // stage s resident
        __syncthreads();                  // all warps done with buffer (s+1)&1
        issue_stage(s + 1, sbst, tid);    // overlaps MMAs below
        stage_mma(sbst + (uint32_t)(s & 1) * STAGE_BYTES + boff0,
                  aAh0, aAl0, (uint32_t)((s & 3) * 128), c);

        if ((s & 3) == 3) {               // epilogue chunk -> g_qkv (fp32, +bias)
            const int nc = s >> 2;
            const int col0 = nc * 128 + warp_n * 32 + (lane & 3) * 2;
            float* base = g_qkv + (size_t)(tok0 + warp_m * 64 + (lane >> 2)) * NQKV
                        + col0;
            const float* bb = s_bias + col0;
            #pragma unroll
            for (int mt = 0; mt < 4; mt++) {
                #pragma unroll
                for (int jt = 0; jt < 4; jt++) {
                    float b0v = bb[jt * 8], b1v = bb[jt * 8 + 1];
                    float* p = base + (size_t)mt * 16 * NQKV + jt * 8;
                    *(float2*)p = make_float2(c[mt][jt][0] + b0v, c[mt][jt][1] + b1v);
                    *(float2*)(p + (size_t)8 * NQKV) =
                        make_float2(c[mt][jt][2] + b0v, c[mt][jt][3] + b1v);
                }
            }
        }
    }
    __syncthreads();   // g_qkv complete; stage 24 loads overlap attention

    // ---- Phase C: attention (fp32), writes o split into Ah/Al
    {
        const float SCALE = 0.08838834764831845f;  // 128^-0.5
        #pragma unroll 1
        for (int pp = 0; pp < 8; pp++) {
            const int p = wid + pp * 8;            // 0..63 (group,head) pairs
            const int g = p >> 1, h = p & 1;
            const float* qb = g_qkv + (size_t)(tok0 + g * 4) * NQKV + h * 128;
            const float* kb = qb + 256;
            const float* vb = qb + 512;

            const int pid = lane >> 1, si = pid >> 2, sj = pid & 3, half = lane & 1;
            const float4* q4 = (const float4*)(qb + si * NQKV + half * 64);
            const float4* k4 = (const float4*)(kb + sj * NQKV + half * 64);
            float partial = 0.f;
            #pragma unroll
            for (int d = 0; d < 16; d++) {
                float4 a = __ldg(q4 + d), b = __ldg(k4 + d);
                partial += a.x * b.x + a.y * b.y + a.z * b.z + a.w * b.w;
            }
            partial += __shfl_xor_sync(0xffffffffu, partial, 1);
            const float sc = partial * SCALE;
            float mx = sc;
            mx = fmaxf(mx, __shfl_xor_sync(0xffffffffu, mx, 2));
            mx = fmaxf(mx, __shfl_xor_sync(0xffffffffu, mx, 4));
            float e = __expf(sc - mx);
            float ssum = e;
            ssum += __shfl_xor_sync(0xffffffffu, ssum, 2);
            ssum += __shfl_xor_sync(0xffffffffu, ssum, 4);
            const float P = e / ssum;
            if (half == 0) s_red[wid * 16 + pid] = P;
            __syncwarp();

            const int d0 = lane * 4;
            float4 vv[4];
            #pragma unroll
            for (int j2 = 0; j2 < 4; j2++)
                vv[j2] = __ldg((const float4*)(vb + j2 * NQKV + d0));
            #pragma unroll
            for (int i2 = 0; i2 < 4; i2++) {
                float4 o4 = make_float4(0.f, 0.f, 0.f, 0.f);
                #pragma unroll
                for (int j2 = 0; j2 < 4; j2++) {
                    const float pij = s_red[wid * 16 + i2 * 4 + j2];
                    o4.x += pij * vv[j2].x; o4.y += pij * vv[j2].y;
                    o4.z += pij * vv[j2].z; o4.w += pij * vv[j2].w;
                }
                uint32_t h0, h1, l0, l1;
                SPLIT4(o4.x, o4.y, o4.z, o4.w, h0, h1, l0, l1);
                const int off = (g * 4 + i2) * SA + h * 128 + d0;
                *(uint2*)(Ah + off) = make_uint2(h0, h1);
                *(uint2*)(Al + off) = make_uint2(l0, l1);
            }
            __syncwarp();
        }
    }

    // ---- Phase E: out projection (stages 24..31), +bias +residual
    for (int s = 24; s < 32; s++) {
        if ((s & 3) == 0) ZERO_C(c);
        CP_WAIT0();
        __syncthreads();                 // also orders attention's Ah/Al writes
        issue_stage(s + 1, sbst, tid);
        stage_mma(sbst + (uint32_t)(s & 1) * STAGE_BYTES + boff0,
                  aAh0, aAl0, (uint32_t)((s & 3) * 128), c);

        if ((s & 3) == 3) {              // epilogue: +bias +residual -> out
            const int nc = (s >> 2) - 6;
            const int col0 = nc * 128 + warp_n * 32 + (lane & 3) * 2;
            const float* bb = s_bias + NQKV + col0;
            #pragma unroll
            for (int mt = 0; mt < 4; mt++) {
                const int row = tok0 + warp_m * 64 + mt * 16 + (lane >> 2);
                #pragma unroll
                for (int jt = 0; jt < 4; jt++) {
                    float b0v = bb[jt * 8], b1v = bb[jt * 8 + 1];
                    size_t gi = (size_t)row * CDIM + col0 + jt * 8;
                    float2 x0 = __ldg((const float2*)(x + gi));
                    float2 x1 = __ldg((const float2*)(x + gi + (size_t)8 * CDIM));
                    *(float2*)(out + gi) =
                        make_float2(c[mt][jt][0] + b0v + x0.x, c[mt][jt][1] + b1v + x0.y);
                    *(float2*)(out + gi + (size_t)8 * CDIM) =
                        make_float2(c[mt][jt][2] + b0v + x1.x, c[mt][jt][3] + b1v + x1.y);
                }
            }
        }
    }
}

// ---------------------------------------------------------------------------
extern "C" void kernel_launch(void* const* d_in, const int* in_sizes, int n_in,
                              void* d_out, int out_size)
{
    const float* x     = (const float*)d_in[0];
    const float* qkv_w = (const float*)d_in[1];
    const float* qkv_b = (const float*)d_in[2];
    const float* out_w = (const float*)d_in[3];
    const float* out_b = (const float*)d_in[4];
    const float* ln_g  = (const float*)d_in[5];
    const float* ln_b  = (const float*)d_in[6];
    float* out = (float*)d_out;

    const int ntok = in_sizes[0] / CDIM;     // 131072
    const int nblk = ntok / MTILE;           // 1024

    ga_prep_w<<<(NQKV + CDIM) * CDIM / 256, 256>>>(qkv_w, out_w);

    cudaFuncSetAttribute(ga_main,
                         cudaFuncAttributeMaxDynamicSharedMemorySize, SMEM_BYTES);
    ga_main<<<nblk, NTHREADS, SMEM_BYTES>>>(x, qkv_b, out_b, ln_g, ln_b, out);
}

// round 11
// speedup vs baseline: 1.4762x; 1.4762x over previous
#include <cuda_runtime.h>
#include <cuda_bf16.h>
#include <stdint.h>
#include <math.h>

// ---------------------------------------------------------------------------
#define CDIM     256
#define MTILE    64           // tokens per CTA -> 2 CTAs per SM
#define NTHREADS 256
#define NQKV     768
#define TOTTOK   131072
#define SA       264          // A tile stride in halves (528B rows; LDSM conflict-free)

#define SB_ROW      80        // B stage row stride bytes (64B data + 16B pad)
#define STAGE_BYTES (256 * SB_ROW)   // 20480: 256 rows x 32 halves

// shared memory layout (bytes) — total 113152 (x2 CTAs = 226304 <= SM smem)
#define S_AH   0                          // 64 x SA halves = 33792
#define S_AL   33792
#define S_BST  67584                      // 2 stages x 20480 = 40960
#define S_BIAS 108544                     // 1024 floats
#define S_RED  112640                     // 128 floats softmax scratch
#define SMEM_BYTES 113152

// ---------------------------------------------------------------------------
__device__ float          g_qkv[(size_t)TOTTOK * NQKV];
__device__ __nv_bfloat16  g_whi[(NQKV + CDIM) * CDIM];
__device__ __nv_bfloat16  g_wlo[(NQKV + CDIM) * CDIM];

// ---------------------------------------------------------------------------
#define MMA16816(c, a, b0, b1) \
    asm volatile("mma.sync.aligned.m16n8k16.row.col.f32.bf16.bf16.f32 " \
        "{%0,%1,%2,%3}, {%4,%5,%6,%7}, {%8,%9}, {%0,%1,%2,%3};" \
        : "+f"((c)[0]), "+f"((c)[1]), "+f"((c)[2]), "+f"((c)[3]) \
        : "r"((a)[0]), "r"((a)[1]), "r"((a)[2]), "r"((a)[3]), \
          "r"(b0), "r"(b1))

#define LDSM4(r, a) \
    asm volatile("ldmatrix.sync.aligned.m8n8.x4.shared.b16 {%0,%1,%2,%3}, [%4];" \
        : "=r"((r)[0]), "=r"((r)[1]), "=r"((r)[2]), "=r"((r)[3]) : "r"(a))

#define CP_ASYNC16(dst, src) \
    asm volatile("cp.async.cg.shared.global [%0], [%1], 16;" \
        :: "r"(dst), "l"(src) : "memory")
#define CP_COMMIT() asm volatile("cp.async.commit_group;" ::: "memory")
#define CP_WAIT0()  asm volatile("cp.async.wait_group 0;" ::: "memory")

#define SPLIT4(a0,a1,a2,a3,HI0,HI1,LO0,LO1) do { \
    __nv_bfloat16 _h0=__float2bfloat16(a0), _h1=__float2bfloat16(a1); \
    __nv_bfloat16 _h2=__float2bfloat16(a2), _h3=__float2bfloat16(a3); \
    __nv_bfloat16 _l0=__float2bfloat16((a0)-__bfloat162float(_h0)); \
    __nv_bfloat16 _l1=__float2bfloat16((a1)-__bfloat162float(_h1)); \
    __nv_bfloat16 _l2=__float2bfloat16((a2)-__bfloat162float(_h2)); \
    __nv_bfloat16 _l3=__float2bfloat16((a3)-__bfloat162float(_h3)); \
    HI0 = ((uint32_t)__bfloat16_as_ushort(_h1) << 16) | __bfloat16_as_ushort(_h0); \
    HI1 = ((uint32_t)__bfloat16_as_ushort(_h3) << 16) | __bfloat16_as_ushort(_h2); \
    LO0 = ((uint32_t)__bfloat16_as_ushort(_l1) << 16) | __bfloat16_as_ushort(_l0); \
    LO1 = ((uint32_t)__bfloat16_as_ushort(_l3) << 16) | __bfloat16_as_ushort(_l2); \
} while (0)

#define ZERO_C(c) do { \
    _Pragma("unroll") for (int mt = 0; mt < 4; mt++) \
    _Pragma("unroll") for (int jt = 0; jt < 4; jt++) \
    _Pragma("unroll") for (int q = 0; q < 4; q++) (c)[mt][jt][q] = 0.f; \
} while (0)

// ---------------------------------------------------------------------------
__global__ void ga_prep_w(const float* __restrict__ qkv_w,
                          const float* __restrict__ out_w) {
    int i = blockIdx.x * blockDim.x + threadIdx.x;     // < 1024*256
    float v = (i < NQKV * CDIM) ? qkv_w[i] : out_w[i - NQKV * CDIM];
    __nv_bfloat16 h = __float2bfloat16(v);
    g_whi[i] = h;
    g_wlo[i] = __float2bfloat16(v - __bfloat162float(h));
}

// ---------------------------------------------------------------------------
// stage s (64 total): chunk = s>>4 (0..2 QKV rows 0/256/512, 3 out rows 768),
// half = (s>>3)&1 (hi/lo), kc = s&7 (32-half k-chunk).
// Stage = 256 rows x 32 halves, row stride 80B, ring buffer (s&1).
__device__ __forceinline__ void issue_stage(int s, uint32_t sbst, int tid) {
    if (s < 64) {
        const int half = (s >> 3) & 1;
        const int kc   = s & 7;
        const int row0 = (s >> 4) * 256;
        const __nv_bfloat16* w = (half ? g_wlo : g_whi)
                               + ((size_t)row0 << 8) + kc * 32;
        const uint32_t dst = sbst + (uint32_t)(s & 1) * STAGE_BYTES;
        #pragma unroll
        for (int k = 0; k < 4; k++) {
            const int i  = tid + k * NTHREADS;        // 0..1023
            const int r  = i >> 2, cq = i & 3;
            CP_ASYNC16(dst + r * SB_ROW + cq * 16,
                       (const void*)(w + ((size_t)r << 8) + cq * 8));
        }
    }
    CP_COMMIT();
}

// one stage: 2 k-steps of 16; hi stages also run the Al term
__device__ __forceinline__ void stage_mma(uint32_t aB0, uint32_t aAh0,
                                          uint32_t aAl0, uint32_t kbase,
                                          int lo_half, float c[4][4][4]) {
    const uint32_t aB1 = aB0 + 16 * SB_ROW;
    #pragma unroll
    for (int ks = 0; ks < 2; ks++) {
        const uint32_t kb = (uint32_t)(ks * 32);
        uint32_t b0[4], b1[4];
        LDSM4(b0, aB0 + kb); LDSM4(b1, aB1 + kb);
        #pragma unroll
        for (int mt = 0; mt < 4; mt++) {
            uint32_t ah[4];
            LDSM4(ah, aAh0 + mt * (16 * SA * 2) + kbase + kb);
            MMA16816(c[mt][0], ah, b0[0], b0[1]);
            MMA16816(c[mt][1], ah, b0[2], b0[3]);
            MMA16816(c[mt][2], ah, b1[0], b1[1]);
            MMA16816(c[mt][3], ah, b1[2], b1[3]);
        }
        if (!lo_half) {
            #pragma unroll
            for (int mt = 0; mt < 4; mt++) {
                uint32_t al[4];
                LDSM4(al, aAl0 + mt * (16 * SA * 2) + kbase + kb);
                MMA16816(c[mt][0], al, b0[0], b0[1]);
                MMA16816(c[mt][1], al, b0[2], b0[3]);
                MMA16816(c[mt][2], al, b1[0], b1[1]);
                MMA16816(c[mt][3], al, b1[2], b1[3]);
            }
        }
    }
}

// ---------------------------------------------------------------------------
__global__ void __launch_bounds__(NTHREADS, 2)
ga_main(const float* __restrict__ x,
        const float* __restrict__ qkv_b,
        const float* __restrict__ out_b,
        const float* __restrict__ ln_g,
        const float* __restrict__ ln_b,
        float* __restrict__ out)
{
    extern __shared__ char smem[];
    __nv_bfloat16* Ah    = (__nv_bfloat16*)(smem + S_AH);
    __nv_bfloat16* Al    = (__nv_bfloat16*)(smem + S_AL);
    float*         s_bias= (float*)(smem + S_BIAS);
    float*         s_red = (float*)(smem + S_RED);

    const int tid  = threadIdx.x;
    const int wid  = tid >> 5;           // 8 warps, each N32 of a 256-wide chunk
    const int lane = tid & 31;
    const int tok0 = blockIdx.x * MTILE;

    const uint32_t sbst = (uint32_t)__cvta_generic_to_shared(smem + S_BST);

    // LDSM lane addresses (M64 tile: every warp spans all 64 rows)
    uint32_t aAh0, aAl0, boff0;
    {
        const int arow  = lane & 15;
        const int akoff = (lane >> 4) << 3;                 // halves
        aAh0 = (uint32_t)__cvta_generic_to_shared(Ah + arow * SA + akoff);
        aAl0 = (uint32_t)__cvta_generic_to_shared(Al + arow * SA + akoff);
        const int brow  = (lane & 7) + ((lane >> 4) << 3);
        const int bkoff = ((lane >> 3) & 1) << 4;           // bytes
        boff0 = (uint32_t)((wid * 32 + brow) * SB_ROW + bkoff);
    }

    // prologue: prefetch stage 0 (overlaps LN below)
    issue_stage(0, sbst, tid);

    for (int i = tid; i < 1024; i += NTHREADS)
        s_bias[i] = (i < NQKV) ? __ldg(qkv_b + i) : __ldg(out_b + i - NQKV);

    // ---- Phase A: LN + bf16 split -> Ah/Al (4 threads per token)
    {
        const int t = tid >> 2, sub = tid & 3;
        const float* xr = x + ((size_t)(tok0 + t) << 8) + sub * 64;
        float s = 0.f, s2 = 0.f;
        #pragma unroll 4
        for (int j = 0; j < 16; j++) {
            float4 v = __ldg((const float4*)xr + j);
            s  += v.x + v.y + v.z + v.w;
            s2 += v.x * v.x + v.y * v.y + v.z * v.z + v.w * v.w;
        }
        s  += __shfl_xor_sync(0xffffffffu, s, 1);
        s2 += __shfl_xor_sync(0xffffffffu, s2, 1);
        s  += __shfl_xor_sync(0xffffffffu, s, 2);
        s2 += __shfl_xor_sync(0xffffffffu, s2, 2);
        const float mean = s * (1.f / 256.f);
        const float rstd = rsqrtf(s2 * (1.f / 256.f) - mean * mean + 1e-5f);
        __nv_bfloat16* ah = Ah + t * SA + sub * 64;
        __nv_bfloat16* al = Al + t * SA + sub * 64;
        #pragma unroll 4
        for (int j = 0; j < 16; j++) {
            const int k = j * 4;
            float4 v  = __ldg((const float4*)xr + j);
            float4 g4 = __ldg((const float4*)(ln_g + sub * 64 + k));
            float4 b4 = __ldg((const float4*)(ln_b + sub * 64 + k));
            float a0 = (v.x - mean) * rstd * g4.x + b4.x;
            float a1 = (v.y - mean) * rstd * g4.y + b4.y;
            float a2 = (v.z - mean) * rstd * g4.z + b4.z;
            float a3 = (v.w - mean) * rstd * g4.w + b4.w;
            uint32_t h0, h1, l0, l1;
            SPLIT4(a0, a1, a2, a3, h0, h1, l0, l1);
            *(uint2*)(ah + k) = make_uint2(h0, h1);
            *(uint2*)(al + k) = make_uint2(l0, l1);
        }
    }

    float c[4][4][4];

    // ---- Phase B: QKV projection (stages 0..47; 16 stages per 256-col chunk)
    for (int s = 0; s < 48; s++) {
        if ((s & 15) == 0) ZERO_C(c);
        CP_WAIT0();                       // stage s resident
        __syncthreads();                  // buffer (s+1)&1 drained (stage s-1)
        issue_stage(s + 1, sbst, tid);    // overlaps MMAs below
        stage_mma(sbst + (uint32_t)(s & 1) * STAGE_BYTES + boff0,
                  aAh0, aAl0, (uint32_t)((s & 7) * 64), (s >> 3) & 1, c);

        if ((s & 15) == 15) {             // epilogue chunk -> g_qkv (fp32, +bias)
            const int nc = s >> 4;
            const int col0 = nc * 256 + wid * 32 + (lane & 3) * 2;
            float* base = g_qkv + (size_t)(tok0 + (lane >> 2)) * NQKV + col0;
            const float* bb = s_bias + col0;
            #pragma unroll
            for (int mt = 0; mt < 4; mt++) {
                #pragma unroll
                for (int jt = 0; jt < 4; jt++) {
                    float b0v = bb[jt * 8], b1v = bb[jt * 8 + 1];
                    float* p = base + (size_t)mt * 16 * NQKV + jt * 8;
                    *(float2*)p = make_float2(c[mt][jt][0] + b0v, c[mt][jt][1] + b1v);
                    *(float2*)(p + (size_t)8 * NQKV) =
                        make_float2(c[mt][jt][2] + b0v, c[mt][jt][3] + b1v);
                }
            }
        }
    }
    __syncthreads();   // g_qkv complete; stage 48 load overlaps attention

    // ---- Phase C: attention (fp32), writes o split into Ah/Al (32 pairs)
    {
        const float SCALE = 0.08838834764831845f;  // 128^-0.5
        #pragma unroll 1
        for (int pp = 0; pp < 4; pp++) {
            const int p = wid + pp * 8;            // 0..31 (group,head) pairs
            const int g = p >> 1, h = p & 1;
            const float* qb = g_qkv + (size_t)(tok0 + g * 4) * NQKV + h * 128;
            const float* kb = qb + 256;
            const float* vb = qb + 512;

            const int pid = lane >> 1, si = pid >> 2, sj = pid & 3, half = lane & 1;
            const float4* q4 = (const float4*)(qb + si * NQKV + half * 64);
            const float4* k4 = (const float4*)(kb + sj * NQKV + half * 64);
            float partial = 0.f;
            #pragma unroll
            for (int d = 0; d < 16; d++) {
                float4 a = __ldg(q4 + d), b = __ldg(k4 + d);
                partial += a.x * b.x + a.y * b.y + a.z * b.z + a.w * b.w;
            }
            partial += __shfl_xor_sync(0xffffffffu, partial, 1);
            const float sc = partial * SCALE;
            float mx = sc;
            mx = fmaxf(mx, __shfl_xor_sync(0xffffffffu, mx, 2));
            mx = fmaxf(mx, __shfl_xor_sync(0xffffffffu, mx, 4));
            float e = __expf(sc - mx);
            float ssum = e;
            ssum += __shfl_xor_sync(0xffffffffu, ssum, 2);
            ssum += __shfl_xor_sync(0xffffffffu, ssum, 4);
            const float P = e / ssum;
            if (half == 0) s_red[wid * 16 + pid] = P;
            __syncwarp();

            const int d0 = lane * 4;
            float4 vv[4];
            #pragma unroll
            for (int j2 = 0; j2 < 4; j2++)
                vv[j2] = __ldg((const float4*)(vb + j2 * NQKV + d0));
            #pragma unroll
            for (int i2 = 0; i2 < 4; i2++) {
                float4 o4 = make_float4(0.f, 0.f, 0.f, 0.f);
                #pragma unroll
                for (int j2 = 0; j2 < 4; j2++) {
                    const float pij = s_red[wid * 16 + i2 * 4 + j2];
                    o4.x += pij * vv[j2].x; o4.y += pij * vv[j2].y;
                    o4.z += pij * vv[j2].z; o4.w += pij * vv[j2].w;
                }
                uint32_t h0, h1, l0, l1;
                SPLIT4(o4.x, o4.y, o4.z, o4.w, h0, h1, l0, l1);
                const int off = (g * 4 + i2) * SA + h * 128 + d0;
                *(uint2*)(Ah + off) = make_uint2(h0, h1);
                *(uint2*)(Al + off) = make_uint2(l0, l1);
            }
            __syncwarp();
        }
    }

    // ---- Phase E: out projection (stages 48..63), +bias +residual
    for (int s = 48; s < 64; s++) {
        if ((s & 15) == 0) ZERO_C(c);
        CP_WAIT0();
        __syncthreads();                 // also orders attention's Ah/Al writes
        issue_stage(s + 1, sbst, tid);
        stage_mma(sbst + (uint32_t)(s & 1) * STAGE_BYTES + boff0,
                  aAh0, aAl0, (uint32_t)((s & 7) * 64), (s >> 3) & 1, c);

        if (s == 63) {                   // epilogue: +bias +residual -> out
            const int col0 = wid * 32 + (lane & 3) * 2;
            const float* bb = s_bias + NQKV + col0;
            #pragma unroll
            for (int mt = 0; mt < 4; mt++) {
                const int row = tok0 + mt * 16 + (lane >> 2);
                #pragma unroll
                for (int jt = 0; jt < 4; jt++) {
                    float b0v = bb[jt * 8], b1v = bb[jt * 8 + 1];
                    size_t gi = (size_t)row * CDIM + col0 + jt * 8;
                    float2 x0 = __ldg((const float2*)(x + gi));
                    float2 x1 = __ldg((const float2*)(x + gi + (size_t)8 * CDIM));
                    *(float2*)(out + gi) =
                        make_float2(c[mt][jt][0] + b0v + x0.x, c[mt][jt][1] + b1v + x0.y);
                    *(float2*)(out + gi + (size_t)8 * CDIM) =
                        make_float2(c[mt][jt][2] + b0v + x1.x, c[mt][jt][3] + b1v + x1.y);
                }
            }
        }
    }
}

// ---------------------------------------------------------------------------
extern "C" void kernel_launch(void* const* d_in, const int* in_sizes, int n_in,
                              void* d_out, int out_size)
{
    const float* x     = (const float*)d_in[0];
    const float* qkv_w = (const float*)d_in[1];
    const float* qkv_b = (const float*)d_in[2];
    const float* out_w = (const float*)d_in[3];
    const float* out_b = (const float*)d_in[4];
    const float* ln_g  = (const float*)d_in[5];
    const float* ln_b  = (const float*)d_in[6];
    float* out = (float*)d_out;

    const int ntok = in_sizes[0] / CDIM;     // 131072
    const int nblk = ntok / MTILE;           // 2048

    ga_prep_w<<<(NQKV + CDIM) * CDIM / 256, 256>>>(qkv_w, out_w);

    cudaFuncSetAttribute(ga_main,
                         cudaFuncAttributeMaxDynamicSharedMemorySize, SMEM_BYTES);
    ga_main<<<nblk, NTHREADS, SMEM_BYTES>>>(x, qkv_b, out_b, ln_g, ln_b, out);
}

// round 12
// speedup vs baseline: 1.8657x; 1.2638x over previous
#include <cuda_runtime.h>
#include <cuda_fp16.h>
#include <stdint.h>
#include <math.h>

// ---------------------------------------------------------------------------
#define CDIM     256
#define MTILE    64           // tokens per CTA -> 2 CTAs per SM
#define NTHREADS 256
#define NQKV     768
#define TOTTOK   131072
#define SA       264          // A tile stride in halves (528B rows; LDSM conflict-free)

#define SB_ROW      80        // B stage row stride bytes (64B data + 16B pad)
#define STAGE_BYTES (256 * SB_ROW)   // 20480: 256 rows x 32 halves

// shared memory layout (bytes) — total 113152 (x2 CTAs fits 227KB)
#define S_AH   0                          // 64 x SA halves = 33792
#define S_AL   33792
#define S_BST  67584                      // 2 stages x 20480 = 40960
#define S_BIAS 108544                     // 1024 floats
#define S_RED  112640                     // 128 floats softmax scratch
#define SMEM_BYTES 113152

// ---------------------------------------------------------------------------
__device__ float   g_qkv[(size_t)TOTTOK * NQKV];
__device__ __half  g_w[(NQKV + CDIM) * CDIM];       // fp16 weights (qkv | out)

// ---------------------------------------------------------------------------
#define MMA16816(c, a, b0, b1) \
    asm volatile("mma.sync.aligned.m16n8k16.row.col.f32.f16.f16.f32 " \
        "{%0,%1,%2,%3}, {%4,%5,%6,%7}, {%8,%9}, {%0,%1,%2,%3};" \
        : "+f"((c)[0]), "+f"((c)[1]), "+f"((c)[2]), "+f"((c)[3]) \
        : "r"((a)[0]), "r"((a)[1]), "r"((a)[2]), "r"((a)[3]), \
          "r"(b0), "r"(b1))

#define LDSM4(r, a) \
    asm volatile("ldmatrix.sync.aligned.m8n8.x4.shared.b16 {%0,%1,%2,%3}, [%4];" \
        : "=r"((r)[0]), "=r"((r)[1]), "=r"((r)[2]), "=r"((r)[3]) : "r"(a))

#define CP_ASYNC16(dst, src) \
    asm volatile("cp.async.cg.shared.global [%0], [%1], 16;" \
        :: "r"(dst), "l"(src) : "memory")
#define CP_COMMIT() asm volatile("cp.async.commit_group;" ::: "memory")
#define CP_WAIT0()  asm volatile("cp.async.wait_group 0;" ::: "memory")

// split 4 fp32 -> packed fp16 hi/lo words (hi = rn(a), lo = rn(a - hi))
#define SPLIT4(a0,a1,a2,a3,HI0,HI1,LO0,LO1) do { \
    __half _h0=__float2half_rn(a0), _h1=__float2half_rn(a1); \
    __half _h2=__float2half_rn(a2), _h3=__float2half_rn(a3); \
    __half _l0=__float2half_rn((a0)-__half2float(_h0)); \
    __half _l1=__float2half_rn((a1)-__half2float(_h1)); \
    __half _l2=__float2half_rn((a2)-__half2float(_h2)); \
    __half _l3=__float2half_rn((a3)-__half2float(_h3)); \
    HI0 = ((uint32_t)__half_as_ushort(_h1) << 16) | __half_as_ushort(_h0); \
    HI1 = ((uint32_t)__half_as_ushort(_h3) << 16) | __half_as_ushort(_h2); \
    LO0 = ((uint32_t)__half_as_ushort(_l1) << 16) | __half_as_ushort(_l0); \
    LO1 = ((uint32_t)__half_as_ushort(_l3) << 16) | __half_as_ushort(_l2); \
} while (0)

#define ZERO_C(c) do { \
    _Pragma("unroll") for (int mt = 0; mt < 4; mt++) \
    _Pragma("unroll") for (int jt = 0; jt < 4; jt++) \
    _Pragma("unroll") for (int q = 0; q < 4; q++) (c)[mt][jt][q] = 0.f; \
} while (0)

// ---------------------------------------------------------------------------
__global__ void ga_prep_w(const float* __restrict__ qkv_w,
                          const float* __restrict__ out_w) {
    int i = blockIdx.x * blockDim.x + threadIdx.x;     // < 1024*256
    float v = (i < NQKV * CDIM) ? qkv_w[i] : out_w[i - NQKV * CDIM];
    g_w[i] = __float2half_rn(v);
}

// ---------------------------------------------------------------------------
// stage s (32 total): chunk = s>>3 (0..2 QKV rows 0/256/512, 3 out rows 768),
// kc = s&7 (32-half k-chunk). Stage = 256 rows x 32 halves, ring buffer (s&1).
__device__ __forceinline__ void issue_stage(int s, uint32_t sbst, int tid) {
    if (s < 32) {
        const int kc   = s & 7;
        const int row0 = (s >> 3) * 256;
        const __half* w = g_w + ((size_t)row0 << 8) + kc * 32;
        const uint32_t dst = sbst + (uint32_t)(s & 1) * STAGE_BYTES;
        #pragma unroll
        for (int k = 0; k < 4; k++) {
            const int i  = tid + k * NTHREADS;        // 0..1023
            const int r  = i >> 2, cq = i & 3;
            CP_ASYNC16(dst + r * SB_ROW + cq * 16,
                       (const void*)(w + ((size_t)r << 8) + cq * 8));
        }
    }
    CP_COMMIT();
}

// one stage: 2 k-steps of 16; both A terms (ah, al) against single fp16 W
__device__ __forceinline__ void stage_mma(uint32_t aB0, uint32_t aAh0,
                                          uint32_t aAl0, uint32_t kbase,
                                          float c[4][4][4]) {
    const uint32_t aB1 = aB0 + 16 * SB_ROW;
    #pragma unroll
    for (int ks = 0; ks < 2; ks++) {
        const uint32_t kb = (uint32_t)(ks * 32);
        uint32_t b0[4], b1[4];
        LDSM4(b0, aB0 + kb); LDSM4(b1, aB1 + kb);
        #pragma unroll
        for (int mt = 0; mt < 4; mt++) {
            uint32_t ah[4];
            LDSM4(ah, aAh0 + mt * (16 * SA * 2) + kbase + kb);
            MMA16816(c[mt][0], ah, b0[0], b0[1]);
            MMA16816(c[mt][1], ah, b0[2], b0[3]);
            MMA16816(c[mt][2], ah, b1[0], b1[1]);
            MMA16816(c[mt][3], ah, b1[2], b1[3]);
        }
        #pragma unroll
        for (int mt = 0; mt < 4; mt++) {
            uint32_t al[4];
            LDSM4(al, aAl0 + mt * (16 * SA * 2) + kbase + kb);
            MMA16816(c[mt][0], al, b0[0], b0[1]);
            MMA16816(c[mt][1], al, b0[2], b0[3]);
            MMA16816(c[mt][2], al, b1[0], b1[1]);
            MMA16816(c[mt][3], al, b1[2], b1[3]);
        }
    }
}

// ---------------------------------------------------------------------------
__global__ void __launch_bounds__(NTHREADS, 2)
ga_main(const float* __restrict__ x,
        const float* __restrict__ qkv_b,
        const float* __restrict__ out_b,
        const float* __restrict__ ln_g,
        const float* __restrict__ ln_b,
        float* __restrict__ out)
{
    extern __shared__ char smem[];
    __half* Ah     = (__half*)(smem + S_AH);
    __half* Al     = (__half*)(smem + S_AL);
    float*  s_bias = (float*)(smem + S_BIAS);
    float*  s_red  = (float*)(smem + S_RED);

    const int tid  = threadIdx.x;
    const int wid  = tid >> 5;           // 8 warps, each N32 of a 256-wide chunk
    const int lane = tid & 31;
    const int tok0 = blockIdx.x * MTILE;

    const uint32_t sbst = (uint32_t)__cvta_generic_to_shared(smem + S_BST);

    // LDSM lane addresses (M64 tile: every warp spans all 64 rows)
    uint32_t aAh0, aAl0, boff0;
    {
        const int arow  = lane & 15;
        const int akoff = (lane >> 4) << 3;                 // halves
        aAh0 = (uint32_t)__cvta_generic_to_shared(Ah + arow * SA + akoff);
        aAl0 = (uint32_t)__cvta_generic_to_shared(Al + arow * SA + akoff);
        const int brow  = (lane & 7) + ((lane >> 4) << 3);
        const int bkoff = ((lane >> 3) & 1) << 4;           // bytes
        boff0 = (uint32_t)((wid * 32 + brow) * SB_ROW + bkoff);
    }

    // prologue: prefetch stage 0 (overlaps LN below)
    issue_stage(0, sbst, tid);

    for (int i = tid; i < 1024; i += NTHREADS)
        s_bias[i] = (i < NQKV) ? __ldg(qkv_b + i) : __ldg(out_b + i - NQKV);

    // ---- Phase A: LN + fp16 split -> Ah/Al (4 threads per token)
    {
        const int t = tid >> 2, sub = tid & 3;
        const float* xr = x + ((size_t)(tok0 + t) << 8) + sub * 64;
        float s = 0.f, s2 = 0.f;
        #pragma unroll 4
        for (int j = 0; j < 16; j++) {
            float4 v = __ldg((const float4*)xr + j);
            s  += v.x + v.y + v.z + v.w;
            s2 += v.x * v.x + v.y * v.y + v.z * v.z + v.w * v.w;
        }
        s  += __shfl_xor_sync(0xffffffffu, s, 1);
        s2 += __shfl_xor_sync(0xffffffffu, s2, 1);
        s  += __shfl_xor_sync(0xffffffffu, s, 2);
        s2 += __shfl_xor_sync(0xffffffffu, s2, 2);
        const float mean = s * (1.f / 256.f);
        const float rstd = rsqrtf(s2 * (1.f / 256.f) - mean * mean + 1e-5f);
        __half* ah = Ah + t * SA + sub * 64;
        __half* al = Al + t * SA + sub * 64;
        #pragma unroll 4
        for (int j = 0; j < 16; j++) {
            const int k = j * 4;
            float4 v  = __ldg((const float4*)xr + j);
            float4 g4 = __ldg((const float4*)(ln_g + sub * 64 + k));
            float4 b4 = __ldg((const float4*)(ln_b + sub * 64 + k));
            float a0 = (v.x - mean) * rstd * g4.x + b4.x;
            float a1 = (v.y - mean) * rstd * g4.y + b4.y;
            float a2 = (v.z - mean) * rstd * g4.z + b4.z;
            float a3 = (v.w - mean) * rstd * g4.w + b4.w;
            uint32_t h0, h1, l0, l1;
            SPLIT4(a0, a1, a2, a3, h0, h1, l0, l1);
            *(uint2*)(ah + k) = make_uint2(h0, h1);
            *(uint2*)(al + k) = make_uint2(l0, l1);
        }
    }

    float c[4][4][4];

    // ---- Phase B: QKV projection (stages 0..23; 8 stages per 256-col chunk)
    for (int s = 0; s < 24; s++) {
        if ((s & 7) == 0) ZERO_C(c);
        CP_WAIT0();                       // stage s resident
        __syncthreads();                  // buffer (s+1)&1 drained (stage s-1)
        issue_stage(s + 1, sbst, tid);    // overlaps MMAs below
        stage_mma(sbst + (uint32_t)(s & 1) * STAGE_BYTES + boff0,
                  aAh0, aAl0, (uint32_t)((s & 7) * 64), c);

        if ((s & 7) == 7) {               // epilogue chunk -> g_qkv (fp32, +bias)
            const int nc = s >> 3;
            const int col0 = nc * 256 + wid * 32 + (lane & 3) * 2;
            float* base = g_qkv + (size_t)(tok0 + (lane >> 2)) * NQKV + col0;
            const float* bb = s_bias + col0;
            #pragma unroll
            for (int mt = 0; mt < 4; mt++) {
                #pragma unroll
                for (int jt = 0; jt < 4; jt++) {
                    float b0v = bb[jt * 8], b1v = bb[jt * 8 + 1];
                    float* p = base + (size_t)mt * 16 * NQKV + jt * 8;
                    *(float2*)p = make_float2(c[mt][jt][0] + b0v, c[mt][jt][1] + b1v);
                    *(float2*)(p + (size_t)8 * NQKV) =
                        make_float2(c[mt][jt][2] + b0v, c[mt][jt][3] + b1v);
                }
            }
        }
    }
    __syncthreads();   // g_qkv complete; stage 24 load overlaps attention

    // ---- Phase C: attention (fp32), writes o split into Ah/Al (32 pairs)
    {
        const float SCALE = 0.08838834764831845f;  // 128^-0.5
        #pragma unroll 1
        for (int pp = 0; pp < 4; pp++) {
            const int p = wid + pp * 8;            // 0..31 (group,head) pairs
            const int g = p >> 1, h = p & 1;
            const float* qb = g_qkv + (size_t)(tok0 + g * 4) * NQKV + h * 128;
            const float* kb = qb + 256;
            const float* vb = qb + 512;

            const int pid = lane >> 1, si = pid >> 2, sj = pid & 3, half = lane & 1;
            const float4* q4 = (const float4*)(qb + si * NQKV + half * 64);
            const float4* k4 = (const float4*)(kb + sj * NQKV + half * 64);
            float partial = 0.f;
            #pragma unroll
            for (int d = 0; d < 16; d++) {
                float4 a = __ldg(q4 + d), b = __ldg(k4 + d);
                partial += a.x * b.x + a.y * b.y + a.z * b.z + a.w * b.w;
            }
            partial += __shfl_xor_sync(0xffffffffu, partial, 1);
            const float sc = partial * SCALE;
            float mx = sc;
            mx = fmaxf(mx, __shfl_xor_sync(0xffffffffu, mx, 2));
            mx = fmaxf(mx, __shfl_xor_sync(0xffffffffu, mx, 4));
            float e = __expf(sc - mx);
            float ssum = e;
            ssum += __shfl_xor_sync(0xffffffffu, ssum, 2);
            ssum += __shfl_xor_sync(0xffffffffu, ssum, 4);
            const float P = e / ssum;
            if (half == 0) s_red[wid * 16 + pid] = P;
            __syncwarp();

            const int d0 = lane * 4;
            float4 vv[4];
            #pragma unroll
            for (int j2 = 0; j2 < 4; j2++)
                vv[j2] = __ldg((const float4*)(vb + j2 * NQKV + d0));
            #pragma unroll
            for (int i2 = 0; i2 < 4; i2++) {
                float4 o4 = make_float4(0.f, 0.f, 0.f, 0.f);
                #pragma unroll
                for (int j2 = 0; j2 < 4; j2++) {
                    const float pij = s_red[wid * 16 + i2 * 4 + j2];
                    o4.x += pij * vv[j2].x; o4.y += pij * vv[j2].y;
                    o4.z += pij * vv[j2].z; o4.w += pij * vv[j2].w;
                }
                uint32_t h0, h1, l0, l1;
                SPLIT4(o4.x, o4.y, o4.z, o4.w, h0, h1, l0, l1);
                const int off = (g * 4 + i2) * SA + h * 128 + d0;
                *(uint2*)(Ah + off) = make_uint2(h0, h1);
                *(uint2*)(Al + off) = make_uint2(l0, l1);
            }
            __syncwarp();
        }
    }

    // ---- Phase E: out projection (stages 24..31), +bias +residual
    for (int s = 24; s < 32; s++) {
        if ((s & 7) == 0) ZERO_C(c);
        CP_WAIT0();
        __syncthreads();                 // also orders attention's Ah/Al writes
        issue_stage(s + 1, sbst, tid);
        stage_mma(sbst + (uint32_t)(s & 1) * STAGE_BYTES + boff0,
                  aAh0, aAl0, (uint32_t)((s & 7) * 64), c);

        if (s == 31) {                   // epilogue: +bias +residual -> out
            const int col0 = wid * 32 + (lane & 3) * 2;
            const float* bb = s_bias + NQKV + col0;
            #pragma unroll
            for (int mt = 0; mt < 4; mt++) {
                const int row = tok0 + mt * 16 + (lane >> 2);
                #pragma unroll
                for (int jt = 0; jt < 4; jt++) {
                    float b0v = bb[jt * 8], b1v = bb[jt * 8 + 1];
                    size_t gi = (size_t)row * CDIM + col0 + jt * 8;
                    float2 x0 = __ldg((const float2*)(x + gi));
                    float2 x1 = __ldg((const float2*)(x + gi + (size_t)8 * CDIM));
                    *(float2*)(out + gi) =
                        make_float2(c[mt][jt][0] + b0v + x0.x, c[mt][jt][1] + b1v + x0.y);
                    *(float2*)(out + gi + (size_t)8 * CDIM) =
                        make_float2(c[mt][jt][2] + b0v + x1.x, c[mt][jt][3] + b1v + x1.y);
                }
            }
        }
    }
}

// ---------------------------------------------------------------------------
extern "C" void kernel_launch(void* const* d_in, const int* in_sizes, int n_in,
                              void* d_out, int out_size)
{
    const float* x     = (const float*)d_in[0];
    const float* qkv_w = (const float*)d_in[1];
    const float* qkv_b = (const float*)d_in[2];
    const float* out_w = (const float*)d_in[3];
    const float* out_b = (const float*)d_in[4];
    const float* ln_g  = (const float*)d_in[5];
    const float* ln_b  = (const float*)d_in[6];
    float* out = (float*)d_out;

    const int ntok = in_sizes[0] / CDIM;     // 131072
    const int nblk = ntok / MTILE;           // 2048

    ga_prep_w<<<(NQKV + CDIM) * CDIM / 256, 256>>>(qkv_w, out_w);

    cudaFuncSetAttribute(ga_main,
                         cudaFuncAttributeMaxDynamicSharedMemorySize, SMEM_BYTES);
    ga_main<<<nblk, NTHREADS, SMEM_BYTES>>>(x, qkv_b, out_b, ln_g, ln_b, out);
}

// round 13
// speedup vs baseline: 2.2204x; 1.1901x over previous
#include <cuda_runtime.h>
#include <cuda_fp16.h>
#include <stdint.h>
#include <math.h>

// ---------------------------------------------------------------------------
#define CDIM     256
#define MTILE    64           // tokens per CTA -> 2 CTAs per SM
#define NTHREADS 256
#define NQKV     768
#define TOTTOK   131072
#define SA       264          // A tile stride in halves (528B rows; LDSM conflict-free)

#define SB_ROW      80        // B stage row stride bytes (64B data + 16B pad)
#define STAGE_BYTES (256 * SB_ROW)   // 20480: 256 rows x 32 halves
#define NRING       3

// shared memory layout (bytes) — total 99840 (x2 CTAs = 199680 <= 227KB)
#define S_AH   0                          // 64 x SA halves = 33792
#define S_BST  33792                      // 3 stages x 20480 = 61440
#define S_BIAS 95232                      // 1024 floats
#define S_RED  99328                      // 128 floats softmax scratch
#define SMEM_BYTES 99840

// ---------------------------------------------------------------------------
__device__ float   g_qkv[(size_t)TOTTOK * NQKV];
__device__ __half  g_w[(NQKV + CDIM) * CDIM];       // fp16 weights (qkv | out)

// ---------------------------------------------------------------------------
#define MMA16816(c, a, b0, b1) \
    asm volatile("mma.sync.aligned.m16n8k16.row.col.f32.f16.f16.f32 " \
        "{%0,%1,%2,%3}, {%4,%5,%6,%7}, {%8,%9}, {%0,%1,%2,%3};" \
        : "+f"((c)[0]), "+f"((c)[1]), "+f"((c)[2]), "+f"((c)[3]) \
        : "r"((a)[0]), "r"((a)[1]), "r"((a)[2]), "r"((a)[3]), \
          "r"(b0), "r"(b1))

#define LDSM4(r, a) \
    asm volatile("ldmatrix.sync.aligned.m8n8.x4.shared.b16 {%0,%1,%2,%3}, [%4];" \
        : "=r"((r)[0]), "=r"((r)[1]), "=r"((r)[2]), "=r"((r)[3]) : "r"(a))

#define CP_ASYNC16(dst, src) \
    asm volatile("cp.async.cg.shared.global [%0], [%1], 16;" \
        :: "r"(dst), "l"(src) : "memory")
#define CP_COMMIT() asm volatile("cp.async.commit_group;" ::: "memory")
#define CP_WAIT1()  asm volatile("cp.async.wait_group 1;" ::: "memory")

// pack 4 fp32 -> 2 fp16x2 words
#define PACK4(a0,a1,a2,a3,W0,W1) do { \
    __half _h0=__float2half_rn(a0), _h1=__float2half_rn(a1); \
    __half _h2=__float2half_rn(a2), _h3=__float2half_rn(a3); \
    W0 = ((uint32_t)__half_as_ushort(_h1) << 16) | __half_as_ushort(_h0); \
    W1 = ((uint32_t)__half_as_ushort(_h3) << 16) | __half_as_ushort(_h2); \
} while (0)

#define ZERO_C(c) do { \
    _Pragma("unroll") for (int mt = 0; mt < 4; mt++) \
    _Pragma("unroll") for (int jt = 0; jt < 4; jt++) \
    _Pragma("unroll") for (int q = 0; q < 4; q++) (c)[mt][jt][q] = 0.f; \
} while (0)

// ---------------------------------------------------------------------------
__global__ void ga_prep_w(const float* __restrict__ qkv_w,
                          const float* __restrict__ out_w) {
    int i = blockIdx.x * blockDim.x + threadIdx.x;     // < 1024*256
    float v = (i < NQKV * CDIM) ? qkv_w[i] : out_w[i - NQKV * CDIM];
    g_w[i] = __float2half_rn(v);
}

// ---------------------------------------------------------------------------
// stage s (32 total): chunk = s>>3 (0..2 QKV rows 0/256/512, 3 out rows 768),
// kc = s&7 (32-half k-chunk). Stage = 256 rows x 32 halves, ring slot s%3.
__device__ __forceinline__ void issue_stage(int s, uint32_t sbst, int tid) {
    if (s < 32) {
        const int kc   = s & 7;
        const int row0 = (s >> 3) * 256;
        const __half* w = g_w + ((size_t)row0 << 8) + kc * 32;
        const uint32_t dst = sbst + (uint32_t)(s % NRING) * STAGE_BYTES;
        #pragma unroll
        for (int k = 0; k < 4; k++) {
            const int i  = tid + k * NTHREADS;        // 0..1023
            const int r  = i >> 2, cq = i & 3;
            CP_ASYNC16(dst + r * SB_ROW + cq * 16,
                       (const void*)(w + ((size_t)r << 8) + cq * 8));
        }
    }
    CP_COMMIT();
}

// one stage: 2 k-steps of 16, single fp16 A term
__device__ __forceinline__ void stage_mma(uint32_t aB0, uint32_t aAh0,
                                          uint32_t kbase, float c[4][4][4]) {
    const uint32_t aB1 = aB0 + 16 * SB_ROW;
    #pragma unroll
    for (int ks = 0; ks < 2; ks++) {
        const uint32_t kb = (uint32_t)(ks * 32);
        uint32_t b0[4], b1[4];
        LDSM4(b0, aB0 + kb); LDSM4(b1, aB1 + kb);
        #pragma unroll
        for (int mt = 0; mt < 4; mt++) {
            uint32_t ah[4];
            LDSM4(ah, aAh0 + mt * (16 * SA * 2) + kbase + kb);
            MMA16816(c[mt][0], ah, b0[0], b0[1]);
            MMA16816(c[mt][1], ah, b0[2], b0[3]);
            MMA16816(c[mt][2], ah, b1[0], b1[1]);
            MMA16816(c[mt][3], ah, b1[2], b1[3]);
        }
    }
}

// ---------------------------------------------------------------------------
__global__ void __launch_bounds__(NTHREADS, 2)
ga_main(const float* __restrict__ x,
        const float* __restrict__ qkv_b,
        const float* __restrict__ out_b,
        const float* __restrict__ ln_g,
        const float* __restrict__ ln_b,
        float* __restrict__ out)
{
    extern __shared__ char smem[];
    __half* Ah     = (__half*)(smem + S_AH);
    float*  s_bias = (float*)(smem + S_BIAS);
    float*  s_red  = (float*)(smem + S_RED);

    const int tid  = threadIdx.x;
    const int wid  = tid >> 5;           // 8 warps, each N32 of a 256-wide chunk
    const int lane = tid & 31;
    const int tok0 = blockIdx.x * MTILE;

    const uint32_t sbst = (uint32_t)__cvta_generic_to_shared(smem + S_BST);

    // LDSM lane addresses (M64 tile: every warp spans all 64 rows)
    uint32_t aAh0, boff0;
    {
        const int arow  = lane & 15;
        const int akoff = (lane >> 4) << 3;                 // halves
        aAh0 = (uint32_t)__cvta_generic_to_shared(Ah + arow * SA + akoff);
        const int brow  = (lane & 7) + ((lane >> 4) << 3);
        const int bkoff = ((lane >> 3) & 1) << 4;           // bytes
        boff0 = (uint32_t)((wid * 32 + brow) * SB_ROW + bkoff);
    }

    // prologue: prefetch stages 0,1 (overlaps LN below)
    issue_stage(0, sbst, tid);
    issue_stage(1, sbst, tid);

    for (int i = tid; i < 1024; i += NTHREADS)
        s_bias[i] = (i < NQKV) ? __ldg(qkv_b + i) : __ldg(out_b + i - NQKV);

    // ---- Phase A: LN -> fp16 A (4 threads per token)
    {
        const int t = tid >> 2, sub = tid & 3;
        const float* xr = x + ((size_t)(tok0 + t) << 8) + sub * 64;
        float s = 0.f, s2 = 0.f;
        #pragma unroll 4
        for (int j = 0; j < 16; j++) {
            float4 v = __ldg((const float4*)xr + j);
            s  += v.x + v.y + v.z + v.w;
            s2 += v.x * v.x + v.y * v.y + v.z * v.z + v.w * v.w;
        }
        s  += __shfl_xor_sync(0xffffffffu, s, 1);
        s2 += __shfl_xor_sync(0xffffffffu, s2, 1);
        s  += __shfl_xor_sync(0xffffffffu, s, 2);
        s2 += __shfl_xor_sync(0xffffffffu, s2, 2);
        const float mean = s * (1.f / 256.f);
        const float rstd = rsqrtf(s2 * (1.f / 256.f) - mean * mean + 1e-5f);
        __half* ah = Ah + t * SA + sub * 64;
        #pragma unroll 4
        for (int j = 0; j < 16; j++) {
            const int k = j * 4;
            float4 v  = __ldg((const float4*)xr + j);
            float4 g4 = __ldg((const float4*)(ln_g + sub * 64 + k));
            float4 b4 = __ldg((const float4*)(ln_b + sub * 64 + k));
            float a0 = (v.x - mean) * rstd * g4.x + b4.x;
            float a1 = (v.y - mean) * rstd * g4.y + b4.y;
            float a2 = (v.z - mean) * rstd * g4.z + b4.z;
            float a3 = (v.w - mean) * rstd * g4.w + b4.w;
            uint32_t w0, w1;
            PACK4(a0, a1, a2, a3, w0, w1);
            *(uint2*)(ah + k) = make_uint2(w0, w1);
        }
    }

    float c[4][4][4];

    // ---- Phase B: QKV projection (stages 0..23; 8 stages per 256-col chunk)
    for (int s = 0; s < 24; s++) {
        if ((s & 7) == 0) ZERO_C(c);
        CP_WAIT1();                       // stage s resident (<=1 group pending)
        __syncthreads();                  // slot (s+2)%3 drained (stage s-1 done)
        issue_stage(s + 2, sbst, tid);    // overlaps MMAs below
        stage_mma(sbst + (uint32_t)(s % NRING) * STAGE_BYTES + boff0,
                  aAh0, (uint32_t)((s & 7) * 64), c);

        if ((s & 7) == 7) {               // epilogue chunk -> g_qkv (fp32, +bias)
            const int nc = s >> 3;
            const int col0 = nc * 256 + wid * 32 + (lane & 3) * 2;
            float* base = g_qkv + (size_t)(tok0 + (lane >> 2)) * NQKV + col0;
            const float* bb = s_bias + col0;
            #pragma unroll
            for (int mt = 0; mt < 4; mt++) {
                #pragma unroll
                for (int jt = 0; jt < 4; jt++) {
                    float b0v = bb[jt * 8], b1v = bb[jt * 8 + 1];
                    float* p = base + (size_t)mt * 16 * NQKV + jt * 8;
                    *(float2*)p = make_float2(c[mt][jt][0] + b0v, c[mt][jt][1] + b1v);
                    *(float2*)(p + (size_t)8 * NQKV) =
                        make_float2(c[mt][jt][2] + b0v, c[mt][jt][3] + b1v);
                }
            }
        }
    }
    __syncthreads();   // g_qkv complete; stages 24,25 in flight overlap attention

    // ---- Phase C: attention (fp32), writes o as fp16 into Ah (32 pairs)
    {
        const float SCALE = 0.08838834764831845f;  // 128^-0.5
        #pragma unroll 1
        for (int pp = 0; pp < 4; pp++) {
            const int p = wid + pp * 8;            // 0..31 (group,head) pairs
            const int g = p >> 1, h = p & 1;
            const float* qb = g_qkv + (size_t)(tok0 + g * 4) * NQKV + h * 128;
            const float* kb = qb + 256;
            const float* vb = qb + 512;

            const int pid = lane >> 1, si = pid >> 2, sj = pid & 3, half = lane & 1;
            const float4* q4 = (const float4*)(qb + si * NQKV + half * 64);
            const float4* k4 = (const float4*)(kb + sj * NQKV + half * 64);
            float partial = 0.f;
            #pragma unroll
            for (int d = 0; d < 16; d++) {
                float4 a = __ldg(q4 + d), b = __ldg(k4 + d);
                partial += a.x * b.x + a.y * b.y + a.z * b.z + a.w * b.w;
            }
            partial += __shfl_xor_sync(0xffffffffu, partial, 1);
            const float sc = partial * SCALE;
            float mx = sc;
            mx = fmaxf(mx, __shfl_xor_sync(0xffffffffu, mx, 2));
            mx = fmaxf(mx, __shfl_xor_sync(0xffffffffu, mx, 4));
            float e = __expf(sc - mx);
            float ssum = e;
            ssum += __shfl_xor_sync(0xffffffffu, ssum, 2);
            ssum += __shfl_xor_sync(0xffffffffu, ssum, 4);
            const float P = e / ssum;
            if (half == 0) s_red[wid * 16 + pid] = P;
            __syncwarp();

            const int d0 = lane * 4;
            float4 vv[4];
            #pragma unroll
            for (int j2 = 0; j2 < 4; j2++)
                vv[j2] = __ldg((const float4*)(vb + j2 * NQKV + d0));
            #pragma unroll
            for (int i2 = 0; i2 < 4; i2++) {
                float4 o4 = make_float4(0.f, 0.f, 0.f, 0.f);
                #pragma unroll
                for (int j2 = 0; j2 < 4; j2++) {
                    const float pij = s_red[wid * 16 + i2 * 4 + j2];
                    o4.x += pij * vv[j2].x; o4.y += pij * vv[j2].y;
                    o4.z += pij * vv[j2].z; o4.w += pij * vv[j2].w;
                }
                uint32_t w0, w1;
                PACK4(o4.x, o4.y, o4.z, o4.w, w0, w1);
                const int off = (g * 4 + i2) * SA + h * 128 + d0;
                *(uint2*)(Ah + off) = make_uint2(w0, w1);
            }
            __syncwarp();
        }
    }

    // ---- Phase E: out projection (stages 24..31), +bias +residual
    for (int s = 24; s < 32; s++) {
        if ((s & 7) == 0) ZERO_C(c);
        CP_WAIT1();
        __syncthreads();                 // also orders attention's Ah writes
        issue_stage(s + 2, sbst, tid);
        stage_mma(sbst + (uint32_t)(s % NRING) * STAGE_BYTES + boff0,
                  aAh0, (uint32_t)((s & 7) * 64), c);

        if (s == 31) {                   // epilogue: +bias +residual -> out
            const int col0 = wid * 32 + (lane & 3) * 2;
            const float* bb = s_bias + NQKV + col0;
            #pragma unroll
            for (int mt = 0; mt < 4; mt++) {
                const int row = tok0 + mt * 16 + (lane >> 2);
                #pragma unroll
                for (int jt = 0; jt < 4; jt++) {
                    float b0v = bb[jt * 8], b1v = bb[jt * 8 + 1];
                    size_t gi = (size_t)row * CDIM + col0 + jt * 8;
                    float2 x0 = __ldg((const float2*)(x + gi));
                    float2 x1 = __ldg((const float2*)(x + gi + (size_t)8 * CDIM));
                    *(float2*)(out + gi) =
                        make_float2(c[mt][jt][0] + b0v + x0.x, c[mt][jt][1] + b1v + x0.y);
                    *(float2*)(out + gi + (size_t)8 * CDIM) =
                        make_float2(c[mt][jt][2] + b0v + x1.x, c[mt][jt][3] + b1v + x1.y);
                }
            }
        }
    }
}

// ---------------------------------------------------------------------------
extern "C" void kernel_launch(void* const* d_in, const int* in_sizes, int n_in,
                              void* d_out, int out_size)
{
    const float* x     = (const float*)d_in[0];
    const float* qkv_w = (const float*)d_in[1];
    const float* qkv_b = (const float*)d_in[2];
    const float* out_w = (const float*)d_in[3];
    const float* out_b = (const float*)d_in[4];
    const float* ln_g  = (const float*)d_in[5];
    const float* ln_b  = (const float*)d_in[6];
    float* out = (float*)d_out;

    const int ntok = in_sizes[0] / CDIM;     // 131072
    const int nblk = ntok / MTILE;           // 2048

    ga_prep_w<<<(NQKV + CDIM) * CDIM / 256, 256>>>(qkv_w, out_w);

    cudaFuncSetAttribute(ga_main,
                         cudaFuncAttributeMaxDynamicSharedMemorySize, SMEM_BYTES);
    ga_main<<<nblk, NTHREADS, SMEM_BYTES>>>(x, qkv_b, out_b, ln_g, ln_b, out);
}

// round 14
// speedup vs baseline: 2.5026x; 1.1271x over previous
#include <cuda_runtime.h>
#include <cuda_fp16.h>
#include <stdint.h>
#include <math.h>

// ---------------------------------------------------------------------------
#define CDIM     256
#define MTILE    32           // tokens per CTA -> QKV fits in smem; 2 CTAs/SM
#define NTHREADS 256
#define NQKV     768
#define SA       264          // A tile stride in halves (LDSM conflict-free)
#define SQ       776          // QKV smem stride in halves (97x16B -> staggered)

#define SB_ROW      80        // B stage row stride bytes (64B data + 16B pad)
#define STAGE_BYTES (256 * SB_ROW)   // 20480: 256 rows x 32 halves
#define NRING       2

// shared memory layout (bytes) — total 112128 (x2 CTAs = 224256)
#define S_AH   0                          // 32 x SA halves = 16896
#define S_QKV  16896                      // 32 x SQ halves = 49664
#define S_BST  66560                      // 2 stages x 20480 = 40960
#define S_BIAS 107520                     // 1024 floats
#define S_RED  111616                     // 128 floats softmax scratch
#define SMEM_BYTES 112128

// ---------------------------------------------------------------------------
__device__ __half  g_w[(NQKV + CDIM) * CDIM];       // fp16 weights (qkv | out)

// ---------------------------------------------------------------------------
#define MMA16816(c, a, b0, b1) \
    asm volatile("mma.sync.aligned.m16n8k16.row.col.f32.f16.f16.f32 " \
        "{%0,%1,%2,%3}, {%4,%5,%6,%7}, {%8,%9}, {%0,%1,%2,%3};" \
        : "+f"((c)[0]), "+f"((c)[1]), "+f"((c)[2]), "+f"((c)[3]) \
        : "r"((a)[0]), "r"((a)[1]), "r"((a)[2]), "r"((a)[3]), \
          "r"(b0), "r"(b1))

#define LDSM4(r, a) \
    asm volatile("ldmatrix.sync.aligned.m8n8.x4.shared.b16 {%0,%1,%2,%3}, [%4];" \
        : "=r"((r)[0]), "=r"((r)[1]), "=r"((r)[2]), "=r"((r)[3]) : "r"(a))

#define CP_ASYNC16(dst, src) \
    asm volatile("cp.async.cg.shared.global [%0], [%1], 16;" \
        :: "r"(dst), "l"(src) : "memory")
#define CP_COMMIT() asm volatile("cp.async.commit_group;" ::: "memory")
#define CP_WAIT0()  asm volatile("cp.async.wait_group 0;" ::: "memory")

// pack 4 fp32 -> 2 fp16x2 words
#define PACK4(a0,a1,a2,a3,W0,W1) do { \
    __half _h0=__float2half_rn(a0), _h1=__float2half_rn(a1); \
    __half _h2=__float2half_rn(a2), _h3=__float2half_rn(a3); \
    W0 = ((uint32_t)__half_as_ushort(_h1) << 16) | __half_as_ushort(_h0); \
    W1 = ((uint32_t)__half_as_ushort(_h3) << 16) | __half_as_ushort(_h2); \
} while (0)

#define ZERO_C(c) do { \
    _Pragma("unroll") for (int mt = 0; mt < 2; mt++) \
    _Pragma("unroll") for (int jt = 0; jt < 4; jt++) \
    _Pragma("unroll") for (int q = 0; q < 4; q++) (c)[mt][jt][q] = 0.f; \
} while (0)

// dot of 8 fp16 pairs held in two uint4
__device__ __forceinline__ float dot8(uint4 a, uint4 b) {
    float acc = 0.f;
    const uint32_t* pa = &a.x;
    const uint32_t* pb = &b.x;
    #pragma unroll
    for (int i = 0; i < 4; i++) {
        float2 fa = __half22float2(*(const __half2*)(pa + i));
        float2 fb = __half22float2(*(const __half2*)(pb + i));
        acc += fa.x * fb.x + fa.y * fb.y;
    }
    return acc;
}

// ---------------------------------------------------------------------------
__global__ void ga_prep_w(const float* __restrict__ qkv_w,
                          const float* __restrict__ out_w) {
    int i = blockIdx.x * blockDim.x + threadIdx.x;     // < 1024*256
    float v = (i < NQKV * CDIM) ? qkv_w[i] : out_w[i - NQKV * CDIM];
    g_w[i] = __float2half_rn(v);
}

// ---------------------------------------------------------------------------
// stage s (32 total): chunk = s>>3 (0..2 QKV rows 0/256/512, 3 out rows 768),
// kc = s&7 (32-half k-chunk). Stage = 256 rows x 32 halves, ring slot s&1.
__device__ __forceinline__ void issue_stage(int s, uint32_t sbst, int tid) {
    if (s < 32) {
        const int kc   = s & 7;
        const int row0 = (s >> 3) * 256;
        const __half* w = g_w + ((size_t)row0 << 8) + kc * 32;
        const uint32_t dst = sbst + (uint32_t)(s & 1) * STAGE_BYTES;
        #pragma unroll
        for (int k = 0; k < 4; k++) {
            const int i  = tid + k * NTHREADS;        // 0..1023
            const int r  = i >> 2, cq = i & 3;
            CP_ASYNC16(dst + r * SB_ROW + cq * 16,
                       (const void*)(w + ((size_t)r << 8) + cq * 8));
        }
    }
    CP_COMMIT();
}

// one stage: 2 k-steps of 16, M32 x N32 warp tile
__device__ __forceinline__ void stage_mma(uint32_t aB0, uint32_t aAh0,
                                          uint32_t kbase, float c[2][4][4]) {
    const uint32_t aB1 = aB0 + 16 * SB_ROW;
    #pragma unroll
    for (int ks = 0; ks < 2; ks++) {
        const uint32_t kb = (uint32_t)(ks * 32);
        uint32_t b0[4], b1[4];
        LDSM4(b0, aB0 + kb); LDSM4(b1, aB1 + kb);
        #pragma unroll
        for (int mt = 0; mt < 2; mt++) {
            uint32_t ah[4];
            LDSM4(ah, aAh0 + mt * (16 * SA * 2) + kbase + kb);
            MMA16816(c[mt][0], ah, b0[0], b0[1]);
            MMA16816(c[mt][1], ah, b0[2], b0[3]);
            MMA16816(c[mt][2], ah, b1[0], b1[1]);
            MMA16816(c[mt][3], ah, b1[2], b1[3]);
        }
    }
}

// ---------------------------------------------------------------------------
__global__ void __launch_bounds__(NTHREADS, 2)
ga_main(const float* __restrict__ x,
        const float* __restrict__ qkv_b,
        const float* __restrict__ out_b,
        const float* __restrict__ ln_g,
        const float* __restrict__ ln_b,
        float* __restrict__ out)
{
    extern __shared__ char smem[];
    __half* Ah     = (__half*)(smem + S_AH);
    __half* Qs     = (__half*)(smem + S_QKV);
    float*  s_bias = (float*)(smem + S_BIAS);
    float*  s_red  = (float*)(smem + S_RED);

    const int tid  = threadIdx.x;
    const int wid  = tid >> 5;           // 8 warps, each N32 of a 256-wide chunk
    const int lane = tid & 31;
    const int tok0 = blockIdx.x * MTILE;

    const uint32_t sbst = (uint32_t)__cvta_generic_to_shared(smem + S_BST);

    // LDSM lane addresses (M32 tile)
    uint32_t aAh0, boff0;
    {
        const int arow  = lane & 15;
        const int akoff = (lane >> 4) << 3;                 // halves
        aAh0 = (uint32_t)__cvta_generic_to_shared(Ah + arow * SA + akoff);
        const int brow  = (lane & 7) + ((lane >> 4) << 3);
        const int bkoff = ((lane >> 3) & 1) << 4;           // bytes
        boff0 = (uint32_t)((wid * 32 + brow) * SB_ROW + bkoff);
    }

    // prologue: prefetch stage 0 (overlaps LN below)
    issue_stage(0, sbst, tid);

    for (int i = tid; i < 1024; i += NTHREADS)
        s_bias[i] = (i < NQKV) ? __ldg(qkv_b + i) : __ldg(out_b + i - NQKV);

    // ---- Phase A: LN -> fp16 A (8 threads per token)
    {
        const int t = tid >> 3, sub = tid & 7;
        const float* xr = x + ((size_t)(tok0 + t) << 8) + sub * 32;
        float s = 0.f, s2 = 0.f;
        #pragma unroll
        for (int j = 0; j < 8; j++) {
            float4 v = __ldg((const float4*)xr + j);
            s  += v.x + v.y + v.z + v.w;
            s2 += v.x * v.x + v.y * v.y + v.z * v.z + v.w * v.w;
        }
        #pragma unroll
        for (int m = 1; m < 8; m <<= 1) {
            s  += __shfl_xor_sync(0xffffffffu, s,  m);
            s2 += __shfl_xor_sync(0xffffffffu, s2, m);
        }
        const float mean = s * (1.f / 256.f);
        const float rstd = rsqrtf(s2 * (1.f / 256.f) - mean * mean + 1e-5f);
        __half* ah = Ah + t * SA + sub * 32;
        #pragma unroll
        for (int j = 0; j < 8; j++) {
            const int k = j * 4;
            float4 v  = __ldg((const float4*)xr + j);
            float4 g4 = __ldg((const float4*)(ln_g + sub * 32 + k));
            float4 b4 = __ldg((const float4*)(ln_b + sub * 32 + k));
            float a0 = (v.x - mean) * rstd * g4.x + b4.x;
            float a1 = (v.y - mean) * rstd * g4.y + b4.y;
            float a2 = (v.z - mean) * rstd * g4.z + b4.z;
            float a3 = (v.w - mean) * rstd * g4.w + b4.w;
            uint32_t w0, w1;
            PACK4(a0, a1, a2, a3, w0, w1);
            *(uint2*)(ah + k) = make_uint2(w0, w1);
        }
    }

    float c[2][4][4];

    // ---- Phase B: QKV projection (stages 0..23), epilogues -> Qs (fp16 smem)
    for (int s = 0; s < 24; s++) {
        if ((s & 7) == 0) ZERO_C(c);
        CP_WAIT0();                       // stage s resident
        __syncthreads();                  // slot (s+1)&1 drained (stage s-1 done)
        issue_stage(s + 1, sbst, tid);    // overlaps MMAs below
        stage_mma(sbst + (uint32_t)(s & 1) * STAGE_BYTES + boff0,
                  aAh0, (uint32_t)((s & 7) * 64), c);

        if ((s & 7) == 7) {               // epilogue chunk -> Qs (fp16, +bias)
            const int nc = s >> 3;
            const int col0 = nc * 256 + wid * 32 + (lane & 3) * 2;
            __half* base = Qs + (lane >> 2) * SQ + col0;
            const float* bb = s_bias + col0;
            #pragma unroll
            for (int mt = 0; mt < 2; mt++) {
                #pragma unroll
                for (int jt = 0; jt < 4; jt++) {
                    float b0v = bb[jt * 8], b1v = bb[jt * 8 + 1];
                    __half* p = base + mt * 16 * SQ + jt * 8;
                    __half lo0 = __float2half_rn(c[mt][jt][0] + b0v);
                    __half lo1 = __float2half_rn(c[mt][jt][1] + b1v);
                    __half hi0 = __float2half_rn(c[mt][jt][2] + b0v);
                    __half hi1 = __float2half_rn(c[mt][jt][3] + b1v);
                    *(uint32_t*)p =
                        ((uint32_t)__half_as_ushort(lo1) << 16) | __half_as_ushort(lo0);
                    *(uint32_t*)(p + 8 * SQ) =
                        ((uint32_t)__half_as_ushort(hi1) << 16) | __half_as_ushort(hi0);
                }
            }
        }
    }
    __syncthreads();   // Qs complete; stage 24 load (issued at s=23) in flight

    // ---- Phase C: attention (fp32 math, fp16 smem QKV), writes o into Ah
    {
        const float SCALE = 0.08838834764831845f;  // 128^-0.5
        #pragma unroll 1
        for (int pp = 0; pp < 2; pp++) {
            const int p = wid + pp * 8;            // 0..15 (group,head) pairs
            const int g = p >> 1, h = p & 1;
            const __half* qb = Qs + (g * 4) * SQ + h * 128;
            const __half* kb = qb + 256;
            const __half* vb = qb + 512;

            const int pid = lane >> 1, si = pid >> 2, sj = pid & 3, half = lane & 1;
            const uint4* q4 = (const uint4*)(qb + si * SQ + half * 64);
            const uint4* k4 = (const uint4*)(kb + sj * SQ + half * 64);
            float partial = 0.f;
            #pragma unroll
            for (int d = 0; d < 8; d++)
                partial += dot8(q4[d], k4[d]);
            partial += __shfl_xor_sync(0xffffffffu, partial, 1);
            const float sc = partial * SCALE;
            float mx = sc;
            mx = fmaxf(mx, __shfl_xor_sync(0xffffffffu, mx, 2));
            mx = fmaxf(mx, __shfl_xor_sync(0xffffffffu, mx, 4));
            float e = __expf(sc - mx);
            float ssum = e;
            ssum += __shfl_xor_sync(0xffffffffu, ssum, 2);
            ssum += __shfl_xor_sync(0xffffffffu, ssum, 4);
            const float P = e / ssum;
            if (half == 0) s_red[wid * 16 + pid] = P;
            __syncwarp();

            const int d0 = lane * 4;               // halves
            float4 vv[4];
            #pragma unroll
            for (int j2 = 0; j2 < 4; j2++) {
                uint2 vr = *(const uint2*)(vb + j2 * SQ + d0);
                float2 v0 = __half22float2(*(const __half2*)&vr.x);
                float2 v1 = __half22float2(*(const __half2*)&vr.y);
                vv[j2] = make_float4(v0.x, v0.y, v1.x, v1.y);
            }
            #pragma unroll
            for (int i2 = 0; i2 < 4; i2++) {
                float4 o4 = make_float4(0.f, 0.f, 0.f, 0.f);
                #pragma unroll
                for (int j2 = 0; j2 < 4; j2++) {
                    const float pij = s_red[wid * 16 + i2 * 4 + j2];
                    o4.x += pij * vv[j2].x; o4.y += pij * vv[j2].y;
                    o4.z += pij * vv[j2].z; o4.w += pij * vv[j2].w;
                }
                uint32_t w0, w1;
                PACK4(o4.x, o4.y, o4.z, o4.w, w0, w1);
                const int off = (g * 4 + i2) * SA + h * 128 + d0;
                *(uint2*)(Ah + off) = make_uint2(w0, w1);
            }
            __syncwarp();
        }
    }

    // ---- Phase E: out projection (stages 24..31), +bias +residual
    for (int s = 24; s < 32; s++) {
        if ((s & 7) == 0) ZERO_C(c);
        CP_WAIT0();
        __syncthreads();                 // also orders attention's Ah writes
        issue_stage(s + 1, sbst, tid);
        stage_mma(sbst + (uint32_t)(s & 1) * STAGE_BYTES + boff0,
                  aAh0, (uint32_t)((s & 7) * 64), c);

        if (s == 31) {                   // epilogue: +bias +residual -> out
            const int col0 = wid * 32 + (lane & 3) * 2;
            const float* bb = s_bias + NQKV + col0;
            #pragma unroll
            for (int mt = 0; mt < 2; mt++) {
                const int row = tok0 + mt * 16 + (lane >> 2);
                #pragma unroll
                for (int jt = 0; jt < 4; jt++) {
                    float b0v = bb[jt * 8], b1v = bb[jt * 8 + 1];
                    size_t gi = (size_t)row * CDIM + col0 + jt * 8;
                    float2 x0 = __ldg((const float2*)(x + gi));
                    float2 x1 = __ldg((const float2*)(x + gi + (size_t)8 * CDIM));
                    *(float2*)(out + gi) =
                        make_float2(c[mt][jt][0] + b0v + x0.x, c[mt][jt][1] + b1v + x0.y);
                    *(float2*)(out + gi + (size_t)8 * CDIM) =
                        make_float2(c[mt][jt][2] + b0v + x1.x, c[mt][jt][3] + b1v + x1.y);
                }
            }
        }
    }
}

// ---------------------------------------------------------------------------
extern "C" void kernel_launch(void* const* d_in, const int* in_sizes, int n_in,
                              void* d_out, int out_size)
{
    const float* x     = (const float*)d_in[0];
    const float* qkv_w = (const float*)d_in[1];
    const float* qkv_b = (const float*)d_in[2];
    const float* out_w = (const float*)d_in[3];
    const float* out_b = (const float*)d_in[4];
    const float* ln_g  = (const float*)d_in[5];
    const float* ln_b  = (const float*)d_in[6];
    float* out = (float*)d_out;

    const int ntok = in_sizes[0] / CDIM;     // 131072
    const int nblk = ntok / MTILE;           // 4096

    ga_prep_w<<<(NQKV + CDIM) * CDIM / 256, 256>>>(qkv_w, out_w);

    cudaFuncSetAttribute(ga_main,
                         cudaFuncAttributeMaxDynamicSharedMemorySize, SMEM_BYTES);
    ga_main<<<nblk, NTHREADS, SMEM_BYTES>>>(x, qkv_b, out_b, ln_g, ln_b, out);
}

// round 15
// speedup vs baseline: 2.6388x; 1.0544x over previous
#include <cuda_runtime.h>
#include <cuda_fp16.h>
#include <stdint.h>
#include <math.h>

// ---------------------------------------------------------------------------
#define CDIM     256
#define MTILE    64           // tokens per CTA; one 512-thread CTA per SM
#define NTHREADS 512
#define NQKV     768
#define SA       264          // A tile stride in halves (LDSM conflict-free)
#define SQ       776          // QKV smem stride in halves (97x16B -> staggered)

#define SB_ROW      80        // B stage row stride bytes (64B data + 16B pad)
#define STAGE_BYTES (256 * SB_ROW)   // 20480: 256 rows x 32 halves
#define NRING       3

// shared memory layout (bytes) — total 199680 (1 CTA/SM)
#define S_AH   0                          // 64 x SA halves = 33792
#define S_QKV  33792                      // 64 x SQ halves = 99328
#define S_BST  133120                     // 3 stages x 20480 = 61440
#define S_BIAS 194560                     // 1024 floats
#define S_RED  198656                     // 256 floats softmax scratch
#define SMEM_BYTES 199680

// ---------------------------------------------------------------------------
__device__ __half  g_w[(NQKV + CDIM) * CDIM];       // fp16 weights (qkv | out)

// ---------------------------------------------------------------------------
#define MMA16816(c, a, b0, b1) \
    asm volatile("mma.sync.aligned.m16n8k16.row.col.f32.f16.f16.f32 " \
        "{%0,%1,%2,%3}, {%4,%5,%6,%7}, {%8,%9}, {%0,%1,%2,%3};" \
        : "+f"((c)[0]), "+f"((c)[1]), "+f"((c)[2]), "+f"((c)[3]) \
        : "r"((a)[0]), "r"((a)[1]), "r"((a)[2]), "r"((a)[3]), \
          "r"(b0), "r"(b1))

#define LDSM4(r, a) \
    asm volatile("ldmatrix.sync.aligned.m8n8.x4.shared.b16 {%0,%1,%2,%3}, [%4];" \
        : "=r"((r)[0]), "=r"((r)[1]), "=r"((r)[2]), "=r"((r)[3]) : "r"(a))

#define CP_ASYNC16(dst, src) \
    asm volatile("cp.async.cg.shared.global [%0], [%1], 16;" \
        :: "r"(dst), "l"(src) : "memory")
#define CP_COMMIT() asm volatile("cp.async.commit_group;" ::: "memory")
#define CP_WAIT1()  asm volatile("cp.async.wait_group 1;" ::: "memory")

// pack 4 fp32 -> 2 fp16x2 words
#define PACK4(a0,a1,a2,a3,W0,W1) do { \
    __half _h0=__float2half_rn(a0), _h1=__float2half_rn(a1); \
    __half _h2=__float2half_rn(a2), _h3=__float2half_rn(a3); \
    W0 = ((uint32_t)__half_as_ushort(_h1) << 16) | __half_as_ushort(_h0); \
    W1 = ((uint32_t)__half_as_ushort(_h3) << 16) | __half_as_ushort(_h2); \
} while (0)

#define ZERO_C(c) do { \
    _Pragma("unroll") for (int mt = 0; mt < 2; mt++) \
    _Pragma("unroll") for (int jt = 0; jt < 4; jt++) \
    _Pragma("unroll") for (int q = 0; q < 4; q++) (c)[mt][jt][q] = 0.f; \
} while (0)

// dot of 8 fp16 pairs held in two uint4
__device__ __forceinline__ float dot8(uint4 a, uint4 b) {
    float acc = 0.f;
    const uint32_t* pa = &a.x;
    const uint32_t* pb = &b.x;
    #pragma unroll
    for (int i = 0; i < 4; i++) {
        float2 fa = __half22float2(*(const __half2*)(pa + i));
        float2 fb = __half22float2(*(const __half2*)(pb + i));
        acc += fa.x * fb.x + fa.y * fb.y;
    }
    return acc;
}

// ---------------------------------------------------------------------------
__global__ void ga_prep_w(const float* __restrict__ qkv_w,
                          const float* __restrict__ out_w) {
    int i = blockIdx.x * blockDim.x + threadIdx.x;     // < 1024*256
    float v = (i < NQKV * CDIM) ? qkv_w[i] : out_w[i - NQKV * CDIM];
    g_w[i] = __float2half_rn(v);
}

// ---------------------------------------------------------------------------
// stage s (32 total): chunk = s>>3 (0..2 QKV rows 0/256/512, 3 out rows 768),
// kc = s&7 (32-half k-chunk). Stage = 256 rows x 32 halves, ring slot s%3.
__device__ __forceinline__ void issue_stage(int s, uint32_t sbst, int tid) {
    if (s < 32) {
        const int kc   = s & 7;
        const int row0 = (s >> 3) * 256;
        const __half* w = g_w + ((size_t)row0 << 8) + kc * 32;
        const uint32_t dst = sbst + (uint32_t)(s % NRING) * STAGE_BYTES;
        #pragma unroll
        for (int k = 0; k < 2; k++) {
            const int i  = tid + k * NTHREADS;        // 0..1023
            const int r  = i >> 2, cq = i & 3;
            CP_ASYNC16(dst + r * SB_ROW + cq * 16,
                       (const void*)(w + ((size_t)r << 8) + cq * 8));
        }
    }
    CP_COMMIT();
}

// one stage: 2 k-steps of 16, M32 x N32 warp tile
__device__ __forceinline__ void stage_mma(uint32_t aB0, uint32_t aAh0,
                                          uint32_t kbase, float c[2][4][4]) {
    const uint32_t aB1 = aB0 + 16 * SB_ROW;
    #pragma unroll
    for (int ks = 0; ks < 2; ks++) {
        const uint32_t kb = (uint32_t)(ks * 32);
        uint32_t b0[4], b1[4];
        LDSM4(b0, aB0 + kb); LDSM4(b1, aB1 + kb);
        #pragma unroll
        for (int mt = 0; mt < 2; mt++) {
            uint32_t ah[4];
            LDSM4(ah, aAh0 + mt * (16 * SA * 2) + kbase + kb);
            MMA16816(c[mt][0], ah, b0[0], b0[1]);
            MMA16816(c[mt][1], ah, b0[2], b0[3]);
            MMA16816(c[mt][2], ah, b1[0], b1[1]);
            MMA16816(c[mt][3], ah, b1[2], b1[3]);
        }
    }
}

// ---------------------------------------------------------------------------
__global__ void __launch_bounds__(NTHREADS, 1)
ga_main(const float* __restrict__ x,
        const float* __restrict__ qkv_b,
        const float* __restrict__ out_b,
        const float* __restrict__ ln_g,
        const float* __restrict__ ln_b,
        float* __restrict__ out)
{
    extern __shared__ char smem[];
    __half* Ah     = (__half*)(smem + S_AH);
    __half* Qs     = (__half*)(smem + S_QKV);
    float*  s_bias = (float*)(smem + S_BIAS);
    float*  s_red  = (float*)(smem + S_RED);

    const int tid  = threadIdx.x;
    const int wid  = tid >> 5;           // 16 warps
    const int lane = tid & 31;
    const int warp_m = wid & 1;          // 2 x M32
    const int warp_n = wid >> 1;         // 8 x N32 -> chunk N = 256
    const int tok0 = blockIdx.x * MTILE;

    const uint32_t sbst = (uint32_t)__cvta_generic_to_shared(smem + S_BST);

    // LDSM lane addresses (M32 tile per warp)
    uint32_t aAh0, boff0;
    {
        const int arow  = warp_m * 32 + (lane & 15);
        const int akoff = (lane >> 4) << 3;                 // halves
        aAh0 = (uint32_t)__cvta_generic_to_shared(Ah + arow * SA + akoff);
        const int brow  = (lane & 7) + ((lane >> 4) << 3);
        const int bkoff = ((lane >> 3) & 1) << 4;           // bytes
        boff0 = (uint32_t)((warp_n * 32 + brow) * SB_ROW + bkoff);
    }

    // prologue: prefetch stages 0,1 (overlap LN below)
    issue_stage(0, sbst, tid);
    issue_stage(1, sbst, tid);

    for (int i = tid; i < 1024; i += NTHREADS)
        s_bias[i] = (i < NQKV) ? __ldg(qkv_b + i) : __ldg(out_b + i - NQKV);

    // ---- Phase A: LN -> fp16 A (8 threads per token, 64 tokens)
    {
        const int t = tid >> 3, sub = tid & 7;
        const float* xr = x + ((size_t)(tok0 + t) << 8) + sub * 32;
        float s = 0.f, s2 = 0.f;
        #pragma unroll
        for (int j = 0; j < 8; j++) {
            float4 v = __ldg((const float4*)xr + j);
            s  += v.x + v.y + v.z + v.w;
            s2 += v.x * v.x + v.y * v.y + v.z * v.z + v.w * v.w;
        }
        #pragma unroll
        for (int m = 1; m < 8; m <<= 1) {
            s  += __shfl_xor_sync(0xffffffffu, s,  m);
            s2 += __shfl_xor_sync(0xffffffffu, s2, m);
        }
        const float mean = s * (1.f / 256.f);
        const float rstd = rsqrtf(s2 * (1.f / 256.f) - mean * mean + 1e-5f);
        __half* ah = Ah + t * SA + sub * 32;
        #pragma unroll
        for (int j = 0; j < 8; j++) {
            const int k = j * 4;
            float4 v  = __ldg((const float4*)xr + j);
            float4 g4 = __ldg((const float4*)(ln_g + sub * 32 + k));
            float4 b4 = __ldg((const float4*)(ln_b + sub * 32 + k));
            float a0 = (v.x - mean) * rstd * g4.x + b4.x;
            float a1 = (v.y - mean) * rstd * g4.y + b4.y;
            float a2 = (v.z - mean) * rstd * g4.z + b4.z;
            float a3 = (v.w - mean) * rstd * g4.w + b4.w;
            uint32_t w0, w1;
            PACK4(a0, a1, a2, a3, w0, w1);
            *(uint2*)(ah + k) = make_uint2(w0, w1);
        }
    }

    float c[2][4][4];

    // ---- Phase B: QKV projection (stages 0..23), epilogues -> Qs (fp16 smem)
    for (int s = 0; s < 24; s++) {
        if ((s & 7) == 0) ZERO_C(c);
        CP_WAIT1();                       // stage s resident (only s+1 may pend)
        __syncthreads();                  // slot (s+2)%3 drained (stage s-1 done)
        issue_stage(s + 2, sbst, tid);    // overlaps MMAs below
        stage_mma(sbst + (uint32_t)(s % NRING) * STAGE_BYTES + boff0,
                  aAh0, (uint32_t)((s & 7) * 64), c);

        if ((s & 7) == 7) {               // epilogue chunk -> Qs (fp16, +bias)
            const int nc = s >> 3;
            const int col0 = nc * 256 + warp_n * 32 + (lane & 3) * 2;
            __half* base = Qs + (warp_m * 32 + (lane >> 2)) * SQ + col0;
            const float* bb = s_bias + col0;
            #pragma unroll
            for (int mt = 0; mt < 2; mt++) {
                #pragma unroll
                for (int jt = 0; jt < 4; jt++) {
                    float b0v = bb[jt * 8], b1v = bb[jt * 8 + 1];
                    __half* p = base + mt * 16 * SQ + jt * 8;
                    __half lo0 = __float2half_rn(c[mt][jt][0] + b0v);
                    __half lo1 = __float2half_rn(c[mt][jt][1] + b1v);
                    __half hi0 = __float2half_rn(c[mt][jt][2] + b0v);
                    __half hi1 = __float2half_rn(c[mt][jt][3] + b1v);
                    *(uint32_t*)p =
                        ((uint32_t)__half_as_ushort(lo1) << 16) | __half_as_ushort(lo0);
                    *(uint32_t*)(p + 8 * SQ) =
                        ((uint32_t)__half_as_ushort(hi1) << 16) | __half_as_ushort(hi0);
                }
            }
        }
    }
    __syncthreads();   // Qs complete; stages 24,25 (issued iters 22,23) in flight

    // ---- Phase C: attention (fp32 math, fp16 smem QKV), writes o into Ah
    {
        const float SCALE = 0.08838834764831845f;  // 128^-0.5
        #pragma unroll 1
        for (int pp = 0; pp < 2; pp++) {
            const int p = wid + pp * 16;           // 0..31 (group,head) pairs
            const int g = p >> 1, h = p & 1;
            const __half* qb = Qs + (g * 4) * SQ + h * 128;
            const __half* kb = qb + 256;
            const __half* vb = qb + 512;

            const int pid = lane >> 1, si = pid >> 2, sj = pid & 3, half = lane & 1;
            const uint4* q4 = (const uint4*)(qb + si * SQ + half * 64);
            const uint4* k4 = (const uint4*)(kb + sj * SQ + half * 64);
            float partial = 0.f;
            #pragma unroll
            for (int d = 0; d < 8; d++)
                partial += dot8(q4[d], k4[d]);
            partial += __shfl_xor_sync(0xffffffffu, partial, 1);
            const float sc = partial * SCALE;
            float mx = sc;
            mx = fmaxf(mx, __shfl_xor_sync(0xffffffffu, mx, 2));
            mx = fmaxf(mx, __shfl_xor_sync(0xffffffffu, mx, 4));
            float e = __expf(sc - mx);
            float ssum = e;
            ssum += __shfl_xor_sync(0xffffffffu, ssum, 2);
            ssum += __shfl_xor_sync(0xffffffffu, ssum, 4);
            const float P = e / ssum;
            if (half == 0) s_red[wid * 16 + pid] = P;
            __syncwarp();

            const int d0 = lane * 4;               // halves
            float4 vv[4];
            #pragma unroll
            for (int j2 = 0; j2 < 4; j2++) {
                uint2 vr = *(const uint2*)(vb + j2 * SQ + d0);
                float2 v0 = __half22float2(*(const __half2*)&vr.x);
                float2 v1 = __half22float2(*(const __half2*)&vr.y);
                vv[j2] = make_float4(v0.x, v0.y, v1.x, v1.y);
            }
            #pragma unroll
            for (int i2 = 0; i2 < 4; i2++) {
                float4 o4 = make_float4(0.f, 0.f, 0.f, 0.f);
                #pragma unroll
                for (int j2 = 0; j2 < 4; j2++) {
                    const float pij = s_red[wid * 16 + i2 * 4 + j2];
                    o4.x += pij * vv[j2].x; o4.y += pij * vv[j2].y;
                    o4.z += pij * vv[j2].z; o4.w += pij * vv[j2].w;
                }
                uint32_t w0, w1;
                PACK4(o4.x, o4.y, o4.z, o4.w, w0, w1);
                const int off = (g * 4 + i2) * SA + h * 128 + d0;
                *(uint2*)(Ah + off) = make_uint2(w0, w1);
            }
            __syncwarp();
        }
    }

    // ---- Phase E: out projection (stages 24..31), +bias +residual
    for (int s = 24; s < 32; s++) {
        if ((s & 7) == 0) ZERO_C(c);
        CP_WAIT1();
        __syncthreads();                 // also orders attention's Ah writes
        issue_stage(s + 2, sbst, tid);
        stage_mma(sbst + (uint32_t)(s % NRING) * STAGE_BYTES + boff0,
                  aAh0, (uint32_t)((s & 7) * 64), c);

        if (s == 31) {                   // epilogue: +bias +residual -> out
            const int col0 = warp_n * 32 + (lane & 3) * 2;
            const float* bb = s_bias + NQKV + col0;
            #pragma unroll
            for (int mt = 0; mt < 2; mt++) {
                const int row = tok0 + warp_m * 32 + mt * 16 + (lane >> 2);
                #pragma unroll
                for (int jt = 0; jt < 4; jt++) {
                    float b0v = bb[jt * 8], b1v = bb[jt * 8 + 1];
                    size_t gi = (size_t)row * CDIM + col0 + jt * 8;
                    float2 x0 = __ldg((const float2*)(x + gi));
                    float2 x1 = __ldg((const float2*)(x + gi + (size_t)8 * CDIM));
                    *(float2*)(out + gi) =
                        make_float2(c[mt][jt][0] + b0v + x0.x, c[mt][jt][1] + b1v + x0.y);
                    *(float2*)(out + gi + (size_t)8 * CDIM) =
                        make_float2(c[mt][jt][2] + b0v + x1.x, c[mt][jt][3] + b1v + x1.y);
                }
            }
        }
    }
}

// ---------------------------------------------------------------------------
extern "C" void kernel_launch(void* const* d_in, const int* in_sizes, int n_in,
                              void* d_out, int out_size)
{
    const float* x     = (const float*)d_in[0];
    const float* qkv_w = (const float*)d_in[1];
    const float* qkv_b = (const float*)d_in[2];
    const float* out_w = (const float*)d_in[3];
    const float* out_b = (const float*)d_in[4];
    const float* ln_g  = (const float*)d_in[5];
    const float* ln_b  = (const float*)d_in[6];
    float* out = (float*)d_out;

    const int ntok = in_sizes[0] / CDIM;     // 131072
    const int nblk = ntok / MTILE;           // 2048

    ga_prep_w<<<(NQKV + CDIM) * CDIM / 256, 256>>>(qkv_w, out_w);

    cudaFuncSetAttribute(ga_main,
                         cudaFuncAttributeMaxDynamicSharedMemorySize, SMEM_BYTES);
    ga_main<<<nblk, NTHREADS, SMEM_BYTES>>>(x, qkv_b, out_b, ln_g, ln_b, out);
}

// round 16
// speedup vs baseline: 3.2235x; 1.2216x over previous
#include <cuda_runtime.h>
#include <cuda_fp16.h>
#include <stdint.h>
#include <math.h>

// ---------------------------------------------------------------------------
#define CDIM     256
#define MTILE    64           // tokens per CTA; one 512-thread CTA per SM
#define NTHREADS 512
#define NQKV     768
#define SA       264          // A tile stride in halves (LDSM conflict-free)
#define SQ       776          // QKV smem stride in halves (97x16B -> staggered)

#define SB_ROW      80        // B stage row stride bytes (64B data + 16B pad)
#define STAGE_BYTES (256 * SB_ROW)   // 20480: 256 rows x 32 halves
#define NRING       3

// shared memory layout (bytes) — total 199680 (1 CTA/SM)
#define S_AH   0                          // 64 x SA halves = 33792
#define S_QKV  33792                      // 64 x SQ halves = 99328
#define S_BST  133120                     // 3 stages x 20480 = 61440
#define S_BIAS 194560                     // 1024 floats
#define S_RED  198656                     // 256 floats softmax scratch
#define SMEM_BYTES 199680

// ---------------------------------------------------------------------------
__device__ __half  g_w[(NQKV + CDIM) * CDIM];       // fp16 weights (qkv | out)

// ---------------------------------------------------------------------------
#define MMA16816(c, a, b0, b1) \
    asm volatile("mma.sync.aligned.m16n8k16.row.col.f32.f16.f16.f32 " \
        "{%0,%1,%2,%3}, {%4,%5,%6,%7}, {%8,%9}, {%0,%1,%2,%3};" \
        : "+f"((c)[0]), "+f"((c)[1]), "+f"((c)[2]), "+f"((c)[3]) \
        : "r"((a)[0]), "r"((a)[1]), "r"((a)[2]), "r"((a)[3]), \
          "r"(b0), "r"(b1))

#define LDSM4(r, a) \
    asm volatile("ldmatrix.sync.aligned.m8n8.x4.shared.b16 {%0,%1,%2,%3}, [%4];" \
        : "=r"((r)[0]), "=r"((r)[1]), "=r"((r)[2]), "=r"((r)[3]) : "r"(a))

#define CP_ASYNC16(dst, src) \
    asm volatile("cp.async.cg.shared.global [%0], [%1], 16;" \
        :: "r"(dst), "l"(src) : "memory")
#define CP_COMMIT() asm volatile("cp.async.commit_group;" ::: "memory")
#define CP_WAIT1()  asm volatile("cp.async.wait_group 1;" ::: "memory")

// 64-thread named barrier (ids 1..8; id 0 reserved for __syncthreads)
#define BAR_GROUP(id) asm volatile("bar.sync %0, 64;" :: "r"(id) : "memory")

// pack 4 fp32 -> 2 fp16x2 words
#define PACK4(a0,a1,a2,a3,W0,W1) do { \
    __half _h0=__float2half_rn(a0), _h1=__float2half_rn(a1); \
    __half _h2=__float2half_rn(a2), _h3=__float2half_rn(a3); \
    W0 = ((uint32_t)__half_as_ushort(_h1) << 16) | __half_as_ushort(_h0); \
    W1 = ((uint32_t)__half_as_ushort(_h3) << 16) | __half_as_ushort(_h2); \
} while (0)

#define ZERO_C(c) do { \
    _Pragma("unroll") for (int mt = 0; mt < 2; mt++) \
    _Pragma("unroll") for (int jt = 0; jt < 4; jt++) \
    _Pragma("unroll") for (int q = 0; q < 4; q++) (c)[mt][jt][q] = 0.f; \
} while (0)

// dot of 8 fp16 pairs held in two uint4
__device__ __forceinline__ float dot8(uint4 a, uint4 b) {
    float acc = 0.f;
    const uint32_t* pa = &a.x;
    const uint32_t* pb = &b.x;
    #pragma unroll
    for (int i = 0; i < 4; i++) {
        float2 fa = __half22float2(*(const __half2*)(pa + i));
        float2 fb = __half22float2(*(const __half2*)(pb + i));
        acc += fa.x * fb.x + fa.y * fb.y;
    }
    return acc;
}

// ---------------------------------------------------------------------------
__global__ void ga_prep_w(const float* __restrict__ qkv_w,
                          const float* __restrict__ out_w) {
    int i = blockIdx.x * blockDim.x + threadIdx.x;     // < 1024*256
    float v = (i < NQKV * CDIM) ? qkv_w[i] : out_w[i - NQKV * CDIM];
    g_w[i] = __float2half_rn(v);
}

// ---------------------------------------------------------------------------
// stage s (32 total): chunk = s>>3 (0..2 QKV rows 0/256/512, 3 out rows 768),
// kc = s&7 (32-half k-chunk). Each 64-thread group loads ONLY its own
// 32-row strip (group g = tid>>6 covers stage rows [g*32, g*32+32)).
// Per-thread cp.async group state makes the wait private to the group.
__device__ __forceinline__ void issue_strip(int s, uint32_t sbst, int tid) {
    if (s < 32) {
        const int g   = tid >> 6;
        const int t64 = tid & 63;
        const int kc  = s & 7;
        const int row0 = (s >> 3) * 256 + g * 32;
        const __half* w = g_w + ((size_t)row0 << 8) + kc * 32;
        const uint32_t dst = sbst + (uint32_t)(s % NRING) * STAGE_BYTES
                           + (uint32_t)(g * 32) * SB_ROW;
        #pragma unroll
        for (int k = 0; k < 2; k++) {
            const int i = t64 + k * 64;        // 0..127 chunks of 16B
            const int r = i >> 2, cq = i & 3;
            CP_ASYNC16(dst + r * SB_ROW + cq * 16,
                       (const void*)(w + ((size_t)r << 8) + cq * 8));
        }
    }
    CP_COMMIT();
}

// one stage: 2 k-steps of 16, M32 x N32 warp tile
__device__ __forceinline__ void stage_mma(uint32_t aB0, uint32_t aAh0,
                                          uint32_t kbase, float c[2][4][4]) {
    const uint32_t aB1 = aB0 + 16 * SB_ROW;
    #pragma unroll
    for (int ks = 0; ks < 2; ks++) {
        const uint32_t kb = (uint32_t)(ks * 32);
        uint32_t b0[4], b1[4];
        LDSM4(b0, aB0 + kb); LDSM4(b1, aB1 + kb);
        #pragma unroll
        for (int mt = 0; mt < 2; mt++) {
            uint32_t ah[4];
            LDSM4(ah, aAh0 + mt * (16 * SA * 2) + kbase + kb);
            MMA16816(c[mt][0], ah, b0[0], b0[1]);
            MMA16816(c[mt][1], ah, b0[2], b0[3]);
            MMA16816(c[mt][2], ah, b1[0], b1[1]);
            MMA16816(c[mt][3], ah, b1[2], b1[3]);
        }
    }
}

// ---------------------------------------------------------------------------
__global__ void __launch_bounds__(NTHREADS, 1)
ga_main(const float* __restrict__ x,
        const float* __restrict__ qkv_b,
        const float* __restrict__ out_b,
        const float* __restrict__ ln_g,
        const float* __restrict__ ln_b,
        float* __restrict__ out)
{
    extern __shared__ char smem[];
    __half* Ah     = (__half*)(smem + S_AH);
    __half* Qs     = (__half*)(smem + S_QKV);
    float*  s_bias = (float*)(smem + S_BIAS);
    float*  s_red  = (float*)(smem + S_RED);

    const int tid  = threadIdx.x;
    const int wid  = tid >> 5;           // 16 warps
    const int lane = tid & 31;
    const int warp_m = wid & 1;          // 2 x M32
    const int warp_n = wid >> 1;         // 8 x N32 -> chunk N = 256; group id
    const int grp1 = warp_n + 1;         // named barrier id 1..8
    const int tok0 = blockIdx.x * MTILE;

    const uint32_t sbst = (uint32_t)__cvta_generic_to_shared(smem + S_BST);

    // LDSM lane addresses (M32 tile per warp)
    uint32_t aAh0, boff0;
    {
        const int arow  = warp_m * 32 + (lane & 15);
        const int akoff = (lane >> 4) << 3;                 // halves
        aAh0 = (uint32_t)__cvta_generic_to_shared(Ah + arow * SA + akoff);
        const int brow  = (lane & 7) + ((lane >> 4) << 3);
        const int bkoff = ((lane >> 3) & 1) << 4;           // bytes
        boff0 = (uint32_t)((warp_n * 32 + brow) * SB_ROW + bkoff);
    }

    // prologue: each group prefetches its strips for stages 0,1
    issue_strip(0, sbst, tid);
    issue_strip(1, sbst, tid);

    for (int i = tid; i < 1024; i += NTHREADS)
        s_bias[i] = (i < NQKV) ? __ldg(qkv_b + i) : __ldg(out_b + i - NQKV);

    // ---- Phase A: LN -> fp16 A (8 threads per token, 64 tokens)
    {
        const int t = tid >> 3, sub = tid & 7;
        const float* xr = x + ((size_t)(tok0 + t) << 8) + sub * 32;
        float s = 0.f, s2 = 0.f;
        #pragma unroll
        for (int j = 0; j < 8; j++) {
            float4 v = __ldg((const float4*)xr + j);
            s  += v.x + v.y + v.z + v.w;
            s2 += v.x * v.x + v.y * v.y + v.z * v.z + v.w * v.w;
        }
        #pragma unroll
        for (int m = 1; m < 8; m <<= 1) {
            s  += __shfl_xor_sync(0xffffffffu, s,  m);
            s2 += __shfl_xor_sync(0xffffffffu, s2, m);
        }
        const float mean = s * (1.f / 256.f);
        const float rstd = rsqrtf(s2 * (1.f / 256.f) - mean * mean + 1e-5f);
        __half* ah = Ah + t * SA + sub * 32;
        #pragma unroll
        for (int j = 0; j < 8; j++) {
            const int k = j * 4;
            float4 v  = __ldg((const float4*)xr + j);
            float4 g4 = __ldg((const float4*)(ln_g + sub * 32 + k));
            float4 b4 = __ldg((const float4*)(ln_b + sub * 32 + k));
            float a0 = (v.x - mean) * rstd * g4.x + b4.x;
            float a1 = (v.y - mean) * rstd * g4.y + b4.y;
            float a2 = (v.z - mean) * rstd * g4.z + b4.z;
            float a3 = (v.w - mean) * rstd * g4.w + b4.w;
            uint32_t w0, w1;
            PACK4(a0, a1, a2, a3, w0, w1);
            *(uint2*)(ah + k) = make_uint2(w0, w1);
        }
    }
    __syncthreads();   // A tile complete for all groups

    float c[2][4][4];

    // ---- Phase B: QKV projection (stages 0..23), 8 independent group rings
    for (int s = 0; s < 24; s++) {
        if ((s & 7) == 0) ZERO_C(c);
        CP_WAIT1();                       // this group's stage-s strip resident
        BAR_GROUP(grp1);                  // both warps done with stage s-1 strip
        issue_strip(s + 2, sbst, tid);    // refill slot (s+2)%3 (private strip)
        stage_mma(sbst + (uint32_t)(s % NRING) * STAGE_BYTES + boff0,
                  aAh0, (uint32_t)((s & 7) * 64), c);

        if ((s & 7) == 7) {               // epilogue chunk -> Qs (fp16, +bias)
            const int nc = s >> 3;
            const int col0 = nc * 256 + warp_n * 32 + (lane & 3) * 2;
            __half* base = Qs + (warp_m * 32 + (lane >> 2)) * SQ + col0;
            const float* bb = s_bias + col0;
            #pragma unroll
            for (int mt = 0; mt < 2; mt++) {
                #pragma unroll
                for (int jt = 0; jt < 4; jt++) {
                    float b0v = bb[jt * 8], b1v = bb[jt * 8 + 1];
                    __half* p = base + mt * 16 * SQ + jt * 8;
                    __half lo0 = __float2half_rn(c[mt][jt][0] + b0v);
                    __half lo1 = __float2half_rn(c[mt][jt][1] + b1v);
                    __half hi0 = __float2half_rn(c[mt][jt][2] + b0v);
                    __half hi1 = __float2half_rn(c[mt][jt][3] + b1v);
                    *(uint32_t*)p =
                        ((uint32_t)__half_as_ushort(lo1) << 16) | __half_as_ushort(lo0);
                    *(uint32_t*)(p + 8 * SQ) =
                        ((uint32_t)__half_as_ushort(hi1) << 16) | __half_as_ushort(hi0);
                }
            }
        }
    }
    __syncthreads();   // Qs complete; stage 24,25 strips in flight per group

    // ---- Phase C: attention (fp32 math, fp16 smem QKV), writes o into Ah
    {
        const float SCALE = 0.08838834764831845f;  // 128^-0.5
        #pragma unroll 1
        for (int pp = 0; pp < 2; pp++) {
            const int p = wid + pp * 16;           // 0..31 (group,head) pairs
            const int g = p >> 1, h = p & 1;
            const __half* qb = Qs + (g * 4) * SQ + h * 128;
            const __half* kb = qb + 256;
            const __half* vb = qb + 512;

            const int pid = lane >> 1, si = pid >> 2, sj = pid & 3, half = lane & 1;
            const uint4* q4 = (const uint4*)(qb + si * SQ + half * 64);
            const uint4* k4 = (const uint4*)(kb + sj * SQ + half * 64);
            float partial = 0.f;
            #pragma unroll
            for (int d = 0; d < 8; d++)
                partial += dot8(q4[d], k4[d]);
            partial += __shfl_xor_sync(0xffffffffu, partial, 1);
            const float sc = partial * SCALE;
            float mx = sc;
            mx = fmaxf(mx, __shfl_xor_sync(0xffffffffu, mx, 2));
            mx = fmaxf(mx, __shfl_xor_sync(0xffffffffu, mx, 4));
            float e = __expf(sc - mx);
            float ssum = e;
            ssum += __shfl_xor_sync(0xffffffffu, ssum, 2);
            ssum += __shfl_xor_sync(0xffffffffu, ssum, 4);
            const float P = e / ssum;
            if (half == 0) s_red[wid * 16 + pid] = P;
            __syncwarp();

            const int d0 = lane * 4;               // halves
            float4 vv[4];
            #pragma unroll
            for (int j2 = 0; j2 < 4; j2++) {
                uint2 vr = *(const uint2*)(vb + j2 * SQ + d0);
                float2 v0 = __half22float2(*(const __half2*)&vr.x);
                float2 v1 = __half22float2(*(const __half2*)&vr.y);
                vv[j2] = make_float4(v0.x, v0.y, v1.x, v1.y);
            }
            #pragma unroll
            for (int i2 = 0; i2 < 4; i2++) {
                float4 o4 = make_float4(0.f, 0.f, 0.f, 0.f);
                #pragma unroll
                for (int j2 = 0; j2 < 4; j2++) {
                    const float pij = s_red[wid * 16 + i2 * 4 + j2];
                    o4.x += pij * vv[j2].x; o4.y += pij * vv[j2].y;
                    o4.z += pij * vv[j2].z; o4.w += pij * vv[j2].w;
                }
                uint32_t w0, w1;
                PACK4(o4.x, o4.y, o4.z, o4.w, w0, w1);
                const int off = (g * 4 + i2) * SA + h * 128 + d0;
                *(uint2*)(Ah + off) = make_uint2(w0, w1);
            }
            __syncwarp();
        }
    }
    __syncthreads();   // o (Ah) complete for all groups

    // ---- Phase E: out projection (stages 24..31), +bias +residual
    for (int s = 24; s < 32; s++) {
        if ((s & 7) == 0) ZERO_C(c);
        CP_WAIT1();
        BAR_GROUP(grp1);
        issue_strip(s + 2, sbst, tid);
        stage_mma(sbst + (uint32_t)(s % NRING) * STAGE_BYTES + boff0,
                  aAh0, (uint32_t)((s & 7) * 64), c);

        if (s == 31) {                   // epilogue: +bias +residual -> out
            const int col0 = warp_n * 32 + (lane & 3) * 2;
            const float* bb = s_bias + NQKV + col0;
            #pragma unroll
            for (int mt = 0; mt < 2; mt++) {
                const int row = tok0 + warp_m * 32 + mt * 16 + (lane >> 2);
                #pragma unroll
                for (int jt = 0; jt < 4; jt++) {
                    float b0v = bb[jt * 8], b1v = bb[jt * 8 + 1];
                    size_t gi = (size_t)row * CDIM + col0 + jt * 8;
                    float2 x0 = __ldg((const float2*)(x + gi));
                    float2 x1 = __ldg((const float2*)(x + gi + (size_t)8 * CDIM));
                    *(float2*)(out + gi) =
                        make_float2(c[mt][jt][0] + b0v + x0.x, c[mt][jt][1] + b1v + x0.y);
                    *(float2*)(out + gi + (size_t)8 * CDIM) =
                        make_float2(c[mt][jt][2] + b0v + x1.x, c[mt][jt][3] + b1v + x1.y);
                }
            }
        }
    }
}

// ---------------------------------------------------------------------------
extern "C" void kernel_launch(void* const* d_in, const int* in_sizes, int n_in,
                              void* d_out, int out_size)
{
    const float* x     = (const float*)d_in[0];
    const float* qkv_w = (const float*)d_in[1];
    const float* qkv_b = (const float*)d_in[2];
    const float* out_w = (const float*)d_in[3];
    const float* out_b = (const float*)d_in[4];
    const float* ln_g  = (const float*)d_in[5];
    const float* ln_b  = (const float*)d_in[6];
    float* out = (float*)d_out;

    const int ntok = in_sizes[0] / CDIM;     // 131072
    const int nblk = ntok / MTILE;           // 2048

    ga_prep_w<<<(NQKV + CDIM) * CDIM / 256, 256>>>(qkv_w, out_w);

    cudaFuncSetAttribute(ga_main,
                         cudaFuncAttributeMaxDynamicSharedMemorySize, SMEM_BYTES);
    ga_main<<<nblk, NTHREADS, SMEM_BYTES>>>(x, qkv_b, out_b, ln_g, ln_b, out);
}